// round 11
// baseline (speedup 1.0000x reference)
#include <cuda_runtime.h>

#define B_   2
#define N_   169
#define NN_  338
#define C_   256
#define H_   4
#define HC_  1024
#define L_   3

typedef unsigned long long ull;

// ---------------- scratch (device globals) ---------------------------------
__device__ float g_x[NN_ * C_];               // running node features
__device__ float g_xl[NN_ * HC_];             // x @ Wl + bl
__device__ float g_xr[NN_ * HC_];             // x @ Wr + br
__device__ float g_agg[B_ * H_ * N_ * C_];    // per-head aggregation partials
__device__ float g_h[NN_ * C_];               // post layernorm
__device__ float g_m[NN_ * 2 * C_];           // mlp hidden
__device__ float g_u[H_ * NN_];               // <att, xl_n> per head
__device__ float g_w[H_ * NN_];               // <att, xr_n> per head

// ---------------- cp.async helpers ------------------------------------------
__device__ __forceinline__ unsigned s2u(const void* p)
{
    return (unsigned)__cvta_generic_to_shared(p);
}
__device__ __forceinline__ void cp8(unsigned dst, const void* src, bool ok)
{
    int sz = ok ? 8 : 0;
    asm volatile("cp.async.ca.shared.global [%0], [%1], 8, %2;"
                 :: "r"(dst), "l"(src), "r"(sz));
}
__device__ __forceinline__ void cp16(unsigned dst, const void* src, bool ok)
{
    int sz = ok ? 16 : 0;
    asm volatile("cp.async.cg.shared.global [%0], [%1], 16, %2;"
                 :: "r"(dst), "l"(src), "r"(sz));
}
__device__ __forceinline__ void cp_commit()
{
    asm volatile("cp.async.commit_group;");
}
__device__ __forceinline__ void cp_wait0()
{
    asm volatile("cp.async.wait_group 0;" ::: "memory");
}

// ---------------- u/w rank-1 terms: u[h,n]=<att_h, xl[n,h,:]>, w likewise ---
__global__ __launch_bounds__(128) void uw_kernel(const float* __restrict__ xl,
                                                 const float* __restrict__ xr,
                                                 const float* __restrict__ att_l,
                                                 float* __restrict__ u,
                                                 float* __restrict__ w)
{
    int n = blockIdx.x;
    int h = threadIdx.x >> 5, lane = threadIdx.x & 31;
    const float4* xlp = (const float4*)&xl[(size_t)n * HC_ + h * C_];
    const float4* xrp = (const float4*)&xr[(size_t)n * HC_ + h * C_];
    const float4* ap  = (const float4*)&att_l[h * C_];
    float su = 0.f, sw = 0.f;
#pragma unroll
    for (int i = 0; i < 2; i++) {
        float4 a = ap[lane + 32 * i];
        float4 vl = xlp[lane + 32 * i];
        float4 vr = xrp[lane + 32 * i];
        su += a.x * vl.x + a.y * vl.y + a.z * vl.z + a.w * vl.w;
        sw += a.x * vr.x + a.y * vr.y + a.z * vr.z + a.w * vr.w;
    }
#pragma unroll
    for (int o = 16; o; o >>= 1) {
        su += __shfl_xor_sync(0xffffffffu, su, o);
        sw += __shfl_xor_sync(0xffffffffu, sw, o);
    }
    if (lane == 0) {
        u[h * NN_ + n] = su;
        w[h * NN_ + n] = sw;
    }
}

// ---------------- fused logits + softmax + aggregation ----------------------
// grid (43 d-tiles, 8 bh), block 384 = 12 warps.
// Phase A: warp = (d-pair p, band j): 2 d-rows x 32 s x 256 c.
//   12 warps/block -> ~7 warps/SMSP at 2.3 blocks/SM: hides LDS latency.
// Softmax: 6-way band combine via shared MX/SS.
// Phase B: warps 0..7 = (d, c-half); all 12 warps stage.
struct AttnSmem {
    union {
        struct {
            float XLs[2][6][32][38];
            float XR[4][256];
            float A4[256];
        } pa;
        struct {
            float Xs[2][32][260];
        } pb;
    } u;
    float AL[4][193];
    float MX[4][6];
    float SS[4][6];
};
#define ATTN_SMEM_BYTES sizeof(AttnSmem)

__global__ __launch_bounds__(384) void attn_agg_kernel(const float* __restrict__ xl,
                                                       const float* __restrict__ xr,
                                                       const float* __restrict__ att_l,
                                                       const float* __restrict__ u,
                                                       const float* __restrict__ w,
                                                       float* __restrict__ agg)
{
    extern __shared__ __align__(16) char smem_raw[];
    AttnSmem* sm = (AttnSmem*)smem_raw;

    int tid = threadIdx.x;
    int lane = tid & 31;
    int wid = tid >> 5;           // 0..11
    int p = wid / 6;              // d-pair 0..1
    int j = wid % 6;              // band 0..5
    int dt = blockIdx.x, bh = blockIdx.y;
    int b = bh >> 2, h = bh & 3;
    int d0 = dt * 4 + p * 2;
    int d1 = d0 + 1;
    bool dok0 = d0 < N_, dok1 = d1 < N_;

    const float* xlh = xl + (size_t)b * N_ * HC_ + h * C_;

    // ---- stage chunk 0 of XLs (async), then XR + A4 (sync LDG, once) ----
#pragma unroll
    for (int i = 0; i < 8; i++) {
        int f = tid + 384 * i;          // 3072 float2
        int st = f >> 9;
        int rem = f & 511;
        int row = rem >> 4;
        int cc = (rem & 15) * 2;
        int s = st * 32 + row;
        bool ok = s < N_;
        cp8(s2u(&sm->u.pa.XLs[0][st][row][cc]),
            &xlh[(size_t)(ok ? s : 0) * HC_ + cc], ok);
    }
    cp_commit();
#pragma unroll
    for (int i = 0; i < 2; i++) {
        int f = tid + 384 * i;          // 512 float2 for XR[4][256]
        if (f < 512) {
            int row = f >> 7;
            int cc = (f & 127) * 2;
            int dr = dt * 4 + row;
            float2 v = make_float2(0.f, 0.f);
            if (dr < N_) v = *(const float2*)&xr[(size_t)(b * N_ + dr) * HC_ + h * C_ + cc];
            *(float2*)&sm->u.pa.XR[row][cc] = v;
        }
    }
    if (tid < 128) {
        float2 a = *(const float2*)&att_l[h * C_ + tid * 2];
        sm->u.pa.A4[tid * 2]     = 0.4f * a.x;
        sm->u.pa.A4[tid * 2 + 1] = 0.4f * a.y;
    }

    ull acc0 = 0ull, acc1 = 0ull;
    const ull msk = 0x7FFFFFFF7FFFFFFFULL;

    // ---------------- Phase A: pipelined over 8 ck-chunks ----------------
#pragma unroll 1
    for (int ch = 0; ch < 8; ch++) {
        cp_wait0();
        __syncthreads();
        if (ch + 1 < 8) {
            int nb = (ch + 1) & 1;
            int ckn = (ch + 1) * 32;
#pragma unroll
            for (int i = 0; i < 8; i++) {
                int f = tid + 384 * i;
                int st = f >> 9;
                int rem = f & 511;
                int row = rem >> 4;
                int cc = (rem & 15) * 2;
                int s = st * 32 + row;
                bool ok = s < N_;
                cp8(s2u(&sm->u.pa.XLs[nb][st][row][cc]),
                    &xlh[(size_t)(ok ? s : 0) * HC_ + ckn + cc], ok);
            }
            cp_commit();
        }
        int bf = ch & 1;
        int ck = ch * 32;
#pragma unroll
        for (int c2 = 0; c2 < 16; c2++) {
            ull r0 = *(const ull*)&sm->u.pa.XR[p * 2][ck + c2 * 2];
            ull r1 = *(const ull*)&sm->u.pa.XR[p * 2 + 1][ck + c2 * 2];
            ull a4 = *(const ull*)&sm->u.pa.A4[ck + c2 * 2];
            ull l = *(const ull*)&sm->u.pa.XLs[bf][j][lane][c2 * 2];
            ull s0, m0, s1, m1;
            asm("add.rn.f32x2 %0, %1, %2;" : "=l"(s0) : "l"(l), "l"(r0));
            asm("add.rn.f32x2 %0, %1, %2;" : "=l"(s1) : "l"(l), "l"(r1));
            asm("and.b64 %0, %1, %2;"      : "=l"(m0) : "l"(s0), "l"(msk));
            asm("and.b64 %0, %1, %2;"      : "=l"(m1) : "l"(s1), "l"(msk));
            asm("fma.rn.f32x2 %0, %1, %2, %0;" : "+l"(acc0) : "l"(m0), "l"(a4));
            asm("fma.rn.f32x2 %0, %1, %2, %0;" : "+l"(acc1) : "l"(m1), "l"(a4));
        }
        __syncthreads();
    }

    // ---- prefetch phase-B chunk 0 now; softmax hides its latency ----
#pragma unroll
    for (int i = 0; i < 6; i++) {
        int f = tid + 384 * i;          // 2048 float4
        if (f < 2048) {
            int row = f >> 6, col4 = f & 63;
            int s = row;
            bool ok = s < N_;
            cp16(s2u(&sm->u.pb.Xs[0][row][col4 * 4]),
                 &xlh[(size_t)(ok ? s : 0) * HC_ + col4 * 4], ok);
        }
    }
    cp_commit();

    // ---------------- softmax: per-warp band stats, 6-way combine --------
    float w_d0 = dok0 ? w[h * NN_ + b * N_ + d0] : 0.f;
    float w_d1 = dok1 ? w[h * NN_ + b * N_ + d1] : 0.f;
    int s_idx = j * 32 + lane;
    float uv = (s_idx < N_) ? u[h * NN_ + b * N_ + s_idx] : 0.f;

    float lg0, lg1;
    {
        float lo = __uint_as_float((unsigned)(acc0 & 0xffffffffu));
        float hi = __uint_as_float((unsigned)(acc0 >> 32));
        float v = 0.6f * (uv + w_d0) + lo + hi;
        if (s_idx >= N_ || s_idx == d0) v = -1e30f;
        lg0 = v;
    }
    {
        float lo = __uint_as_float((unsigned)(acc1 & 0xffffffffu));
        float hi = __uint_as_float((unsigned)(acc1 >> 32));
        float v = 0.6f * (uv + w_d1) + lo + hi;
        if (s_idx >= N_ || s_idx == d1) v = -1e30f;
        lg1 = v;
    }
    float mx0 = lg0, mx1 = lg1;
#pragma unroll
    for (int o = 16; o; o >>= 1) {
        mx0 = fmaxf(mx0, __shfl_xor_sync(0xffffffffu, mx0, o));
        mx1 = fmaxf(mx1, __shfl_xor_sync(0xffffffffu, mx1, o));
    }
    if (lane == 0) {
        sm->MX[p * 2][j]     = mx0;
        sm->MX[p * 2 + 1][j] = mx1;
    }
    __syncthreads();
    float gmx0 = -1e30f, gmx1 = -1e30f;
#pragma unroll
    for (int k = 0; k < 6; k++) {
        gmx0 = fmaxf(gmx0, sm->MX[p * 2][k]);
        gmx1 = fmaxf(gmx1, sm->MX[p * 2 + 1][k]);
    }
    float e0 = __expf(lg0 - gmx0);
    float e1 = __expf(lg1 - gmx1);
    float s0 = e0, s1 = e1;
#pragma unroll
    for (int o = 16; o; o >>= 1) {
        s0 += __shfl_xor_sync(0xffffffffu, s0, o);
        s1 += __shfl_xor_sync(0xffffffffu, s1, o);
    }
    if (lane == 0) {
        sm->SS[p * 2][j]     = s0;
        sm->SS[p * 2 + 1][j] = s1;
    }
    __syncthreads();
    float t0 = 0.f, t1 = 0.f;
#pragma unroll
    for (int k = 0; k < 6; k++) {
        t0 += sm->SS[p * 2][k];
        t1 += sm->SS[p * 2 + 1][k];
    }
    sm->AL[p * 2][s_idx]     = e0 * (1.f / (t0 + 1e-16f));
    sm->AL[p * 2 + 1][s_idx] = e1 * (1.f / (t1 + 1e-16f));
    // AL write->read ordering: __syncthreads at head of phase-B loop

    // ---------------- Phase B: warps 0..7 = (d, c-half) ------------------
    int bd = wid >> 1;            // d-row 0..3 (valid for wid<8)
    int chf = wid & 1;            // c-half
    bool bact = wid < 8;
    int cb = chf * 128 + lane * 4;
    int dd = dt * 4 + bd;
    float4 accB = make_float4(0.f, 0.f, 0.f, 0.f);

#pragma unroll 1
    for (int ch = 0; ch < 6; ch++) {
        cp_wait0();
        __syncthreads();
        if (ch + 1 < 6) {
            int nb = (ch + 1) & 1;
            int skn = (ch + 1) * 32;
#pragma unroll
            for (int i = 0; i < 6; i++) {
                int f = tid + 384 * i;
                if (f < 2048) {
                    int row = f >> 6, col4 = f & 63;
                    int s = skn + row;
                    bool ok = s < N_;
                    cp16(s2u(&sm->u.pb.Xs[nb][row][col4 * 4]),
                         &xlh[(size_t)(ok ? s : 0) * HC_ + col4 * 4], ok);
                }
            }
            cp_commit();
        }
        if (bact) {
            int bf = ch & 1;
            int sk = ch * 32;
#pragma unroll
            for (int k = 0; k < 32; k++) {
                float av = sm->AL[bd][sk + k];
                float4 x = *(const float4*)&sm->u.pb.Xs[bf][k][cb];
                accB.x = fmaf(av, x.x, accB.x); accB.y = fmaf(av, x.y, accB.y);
                accB.z = fmaf(av, x.z, accB.z); accB.w = fmaf(av, x.w, accB.w);
            }
        }
        __syncthreads();
    }

    if (bact && dd < N_)
        *(float4*)&agg[((size_t)bh * N_ + dd) * C_ + cb] = accB;
}

// ---------------- fused xl/xr GEMM, cp.async double-buffered ----------------
__global__ __launch_bounds__(256) void gemm_dual(const float* __restrict__ A,
                                                 const float* __restrict__ B1,
                                                 const float* __restrict__ c1,
                                                 float* __restrict__ o1,
                                                 const float* __restrict__ B2,
                                                 const float* __restrict__ c2p,
                                                 float* __restrict__ o2,
                                                 int M, int K)
{
    __shared__ __align__(16) float As[2][64][36];
    __shared__ __align__(16) float Bs[2][32][36];

    const float* Bm;
    const float* bias;
    float* out;
    int n0;
    if (blockIdx.x < 32) { Bm = B1; bias = c1;  out = o1; n0 = blockIdx.x * 32; }
    else                 { Bm = B2; bias = c2p; out = o2; n0 = (blockIdx.x - 32) * 32; }

    int tid = threadIdx.x;
    int tx = tid & 15, ty = tid >> 4;
    int m0 = blockIdx.y * 64;

    int a_row = tid >> 2, a_c4a = (tid & 3) * 2;
    int b_row = tid >> 3, b_c4 = tid & 7;

    {
        bool okA = (m0 + a_row) < M;
        const float* srcA = &A[(size_t)(m0 + (okA ? a_row : 0)) * K + a_c4a * 4];
        cp16(s2u(&As[0][a_row][a_c4a * 4]), srcA, okA);
        cp16(s2u(&As[0][a_row][(a_c4a + 1) * 4]), srcA + 4, okA);
        cp16(s2u(&Bs[0][b_row][b_c4 * 4]),
             &Bm[(size_t)b_row * HC_ + n0 + b_c4 * 4], true);
    }
    cp_commit();

    float acc[4][2];
#pragma unroll
    for (int i = 0; i < 4; i++) { acc[i][0] = 0.f; acc[i][1] = 0.f; }

    int nch = K / 32;
#pragma unroll 1
    for (int ch = 0; ch < nch; ch++) {
        cp_wait0();
        __syncthreads();
        if (ch + 1 < nch) {
            int nb = (ch + 1) & 1;
            int kkn = (ch + 1) * 32;
            bool okA = (m0 + a_row) < M;
            const float* srcA = &A[(size_t)(m0 + (okA ? a_row : 0)) * K + kkn + a_c4a * 4];
            cp16(s2u(&As[nb][a_row][a_c4a * 4]), srcA, okA);
            cp16(s2u(&As[nb][a_row][(a_c4a + 1) * 4]), srcA + 4, okA);
            cp16(s2u(&Bs[nb][b_row][b_c4 * 4]),
                 &Bm[(size_t)(kkn + b_row) * HC_ + n0 + b_c4 * 4], true);
            cp_commit();
        }
        int bf = ch & 1;
#pragma unroll
        for (int k = 0; k < 32; k++) {
            float a0 = As[bf][ty * 4 + 0][k];
            float a1 = As[bf][ty * 4 + 1][k];
            float a2 = As[bf][ty * 4 + 2][k];
            float a3 = As[bf][ty * 4 + 3][k];
            float2 bv = *(const float2*)&Bs[bf][k][tx * 2];
            acc[0][0] = fmaf(a0, bv.x, acc[0][0]); acc[0][1] = fmaf(a0, bv.y, acc[0][1]);
            acc[1][0] = fmaf(a1, bv.x, acc[1][0]); acc[1][1] = fmaf(a1, bv.y, acc[1][1]);
            acc[2][0] = fmaf(a2, bv.x, acc[2][0]); acc[2][1] = fmaf(a2, bv.y, acc[2][1]);
            acc[3][0] = fmaf(a3, bv.x, acc[3][0]); acc[3][1] = fmaf(a3, bv.y, acc[3][1]);
        }
        __syncthreads();
    }

    float b0 = bias[n0 + tx * 2], b1 = bias[n0 + tx * 2 + 1];
#pragma unroll
    for (int i = 0; i < 4; i++) {
        int r = m0 + ty * 4 + i;
        if (r < M) {
            out[(size_t)r * HC_ + n0 + tx * 2]     = acc[i][0] + b0;
            out[(size_t)r * HC_ + n0 + tx * 2 + 1] = acc[i][1] + b1;
        }
    }
}

// ---------------- generic 32x32 GEMM, cp.async double-buffered --------------
// mode: 1 relu, 2 residual: out = resid + acc + bias
__global__ void gemm_kernel(const float* __restrict__ A,
                            const float* __restrict__ Bm,
                            const float* __restrict__ bias,
                            const float* __restrict__ resid,
                            float* __restrict__ out,
                            int M, int N, int K, int mode)
{
    __shared__ __align__(16) float As[2][32][36];
    __shared__ __align__(16) float Bs[2][32][36];
    int tid = threadIdx.x;
    int tx = tid & 15, ty = tid >> 4;
    int m0 = blockIdx.y * 32;
    int n0 = blockIdx.x * 32;
    int lr = tid >> 3, lc4 = tid & 7;
    float a00 = 0.f, a01 = 0.f, a10 = 0.f, a11 = 0.f;

    {
        bool okA = (m0 + lr) < M;
        cp16(s2u(&As[0][lr][lc4 * 4]),
             &A[(size_t)(m0 + (okA ? lr : 0)) * K + lc4 * 4], okA);
        cp16(s2u(&Bs[0][lr][lc4 * 4]),
             &Bm[(size_t)lr * N + n0 + lc4 * 4], true);
    }
    cp_commit();

    int nch = K / 32;
#pragma unroll 1
    for (int ch = 0; ch < nch; ch++) {
        cp_wait0();
        __syncthreads();
        if (ch + 1 < nch) {
            int nb = (ch + 1) & 1;
            int kkn = (ch + 1) * 32;
            bool okA = (m0 + lr) < M;
            cp16(s2u(&As[nb][lr][lc4 * 4]),
                 &A[(size_t)(m0 + (okA ? lr : 0)) * K + kkn + lc4 * 4], okA);
            cp16(s2u(&Bs[nb][lr][lc4 * 4]),
                 &Bm[(size_t)(kkn + lr) * N + n0 + lc4 * 4], true);
            cp_commit();
        }
        int bf = ch & 1;
#pragma unroll
        for (int k = 0; k < 32; k++) {
            float av0 = As[bf][ty][k],      av1 = As[bf][ty + 16][k];
            float bv0 = Bs[bf][k][tx],      bv1 = Bs[bf][k][tx + 16];
            a00 = fmaf(av0, bv0, a00);  a01 = fmaf(av0, bv1, a01);
            a10 = fmaf(av1, bv0, a10);  a11 = fmaf(av1, bv1, a11);
        }
        __syncthreads();
    }

    int r0 = m0 + ty, r1 = m0 + ty + 16;
    int c0 = n0 + tx, c1 = n0 + tx + 16;
    float b0 = bias[c0], b1 = bias[c1];
    if (mode == 1) {
        if (r0 < M) { out[r0 * N + c0] = fmaxf(a00 + b0, 0.f); out[r0 * N + c1] = fmaxf(a01 + b1, 0.f); }
        if (r1 < M) { out[r1 * N + c0] = fmaxf(a10 + b0, 0.f); out[r1 * N + c1] = fmaxf(a11 + b1, 0.f); }
    } else {
        if (r0 < M) {
            out[r0 * N + c0] = resid[r0 * N + c0] + a00 + b0;
            out[r0 * N + c1] = resid[r0 * N + c1] + a01 + b1;
        }
        if (r1 < M) {
            out[r1 * N + c0] = resid[r1 * N + c0] + a10 + b0;
            out[r1 * N + c1] = resid[r1 * N + c1] + a11 + b1;
        }
    }
}

// ---------------- head-mean + bias + layernorm (4 rows/block, float4) -------
__global__ __launch_bounds__(256) void ln_kernel(const float* __restrict__ agg,
                                                 const float* __restrict__ bias_l,
                                                 const float* __restrict__ g,
                                                 const float* __restrict__ bt,
                                                 float* __restrict__ out)
{
    int ty = threadIdx.x >> 6;
    int tx = threadIdx.x & 63;
    int wq = threadIdx.x >> 5;
    int n = blockIdx.x * 4 + ty;
    bool ok = n < NN_;
    int b = (n >= N_) ? 1 : 0;
    int d = n - b * N_;

    float4 v = make_float4(0.f, 0.f, 0.f, 0.f);
    if (ok) {
#pragma unroll
        for (int h = 0; h < H_; h++) {
            float4 t = *(const float4*)&agg[((size_t)(b * H_ + h) * N_ + d) * C_ + tx * 4];
            v.x += t.x; v.y += t.y; v.z += t.z; v.w += t.w;
        }
        float4 bb = *(const float4*)&bias_l[tx * 4];
        v.x = 0.25f * v.x + bb.x; v.y = 0.25f * v.y + bb.y;
        v.z = 0.25f * v.z + bb.z; v.w = 0.25f * v.w + bb.w;
    }

    __shared__ float red[8];
    float s = v.x + v.y + v.z + v.w;
#pragma unroll
    for (int o = 16; o; o >>= 1) s += __shfl_xor_sync(0xffffffffu, s, o);
    if ((threadIdx.x & 31) == 0) red[wq] = s;
    __syncthreads();
    float mu = (red[ty * 2] + red[ty * 2 + 1]) * (1.f / C_);
    __syncthreads();

    float4 dd = make_float4(v.x - mu, v.y - mu, v.z - mu, v.w - mu);
    float s2 = dd.x * dd.x + dd.y * dd.y + dd.z * dd.z + dd.w * dd.w;
#pragma unroll
    for (int o = 16; o; o >>= 1) s2 += __shfl_xor_sync(0xffffffffu, s2, o);
    if ((threadIdx.x & 31) == 0) red[wq] = s2;
    __syncthreads();
    float rstd = rsqrtf((red[ty * 2] + red[ty * 2 + 1]) * (1.f / C_) + 1e-5f);

    if (ok) {
        float4 gg = *(const float4*)&g[tx * 4];
        float4 tb = *(const float4*)&bt[tx * 4];
        float4 o4;
        o4.x = dd.x * rstd * gg.x + tb.x;
        o4.y = dd.y * rstd * gg.y + tb.y;
        o4.z = dd.z * rstd * gg.z + tb.z;
        o4.w = dd.w * rstd * gg.w + tb.w;
        *(float4*)&out[(size_t)n * C_ + tx * 4] = o4;
    }
}

// ---------------- final mean pool per graph ----------------------------------
__global__ void pool_kernel(const float* __restrict__ x, float* __restrict__ out)
{
    int b = blockIdx.x, t = threadIdx.x;
    float s = 0.f;
#pragma unroll 13
    for (int d = 0; d < N_; d++) s += x[(b * N_ + d) * C_ + t];
    out[b * C_ + t] = s * (1.f / N_);
}

// ---------------- host launcher -----------------------------------------------
extern "C" void kernel_launch(void* const* d_in, const int* in_sizes, int n_in,
                              void* d_out, int out_size)
{
    const float* x    = (const float*)d_in[0];
    const float* Wl   = (const float*)d_in[1];
    const float* bl   = (const float*)d_in[2];
    const float* Wr   = (const float*)d_in[3];
    const float* br   = (const float*)d_in[4];
    const float* att  = (const float*)d_in[5];
    const float* bias = (const float*)d_in[6];
    const float* lng  = (const float*)d_in[7];
    const float* lnb  = (const float*)d_in[8];
    const float* W1   = (const float*)d_in[9];
    const float* b1   = (const float*)d_in[10];
    const float* W2   = (const float*)d_in[11];
    const float* b2   = (const float*)d_in[12];

    float *bx, *bxl, *bxr, *bag, *bh, *bm, *bu, *bw;
    cudaGetSymbolAddress((void**)&bx,  g_x);
    cudaGetSymbolAddress((void**)&bxl, g_xl);
    cudaGetSymbolAddress((void**)&bxr, g_xr);
    cudaGetSymbolAddress((void**)&bag, g_agg);
    cudaGetSymbolAddress((void**)&bh,  g_h);
    cudaGetSymbolAddress((void**)&bm,  g_m);
    cudaGetSymbolAddress((void**)&bu,  g_u);
    cudaGetSymbolAddress((void**)&bw,  g_w);

    static int attr_done = 0;
    if (!attr_done) {
        cudaFuncSetAttribute(attn_agg_kernel,
                             cudaFuncAttributeMaxDynamicSharedMemorySize,
                             (int)ATTN_SMEM_BYTES);
        attr_done = 1;
    }

    for (int l = 0; l < L_; l++) {
        const float* xin = (l == 0) ? x : bx;
        gemm_dual<<<dim3(64, 6), 256>>>(xin,
                                        Wl + l * C_ * HC_, bl + l * HC_, bxl,
                                        Wr + l * C_ * HC_, br + l * HC_, bxr,
                                        NN_, C_);
        uw_kernel<<<NN_, 128>>>(bxl, bxr, att + l * H_ * C_, bu, bw);
        attn_agg_kernel<<<dim3(43, 8), 384, ATTN_SMEM_BYTES>>>(
            bxl, bxr, att + l * H_ * C_, bu, bw, bag);
        ln_kernel<<<85, 256>>>(bag, bias + l * C_, lng + l * C_, lnb + l * C_, bh);
        gemm_kernel<<<dim3(16, 11), 256>>>(bh, W1 + l * C_ * 2 * C_, b1 + l * 2 * C_,
                                           nullptr, bm, NN_, 2 * C_, C_, 1);
        gemm_kernel<<<dim3(8, 11), 256>>>(bm, W2 + l * 2 * C_ * C_, b2 + l * C_,
                                          xin, bx, NN_, C_, 2 * C_, 2);
    }

    pool_kernel<<<B_, 256>>>(bx, (float*)d_out);
}

// round 12
// speedup vs baseline: 1.1692x; 1.1692x over previous
#include <cuda_runtime.h>

#define B_   2
#define N_   169
#define NN_  338
#define C_   256
#define H_   4
#define HC_  1024
#define L_   3

typedef unsigned long long ull;

// ---------------- scratch (device globals) ---------------------------------
__device__ float g_x[NN_ * C_];               // running node features
__device__ float g_xl[NN_ * HC_];             // x @ Wl + bl
__device__ float g_xr[NN_ * HC_];             // x @ Wr + br
__device__ float g_agg[B_ * H_ * N_ * C_];    // per-head aggregation partials
__device__ float g_h[NN_ * C_];               // post layernorm
__device__ float g_m[NN_ * 2 * C_];           // mlp hidden
__device__ float g_u[H_ * NN_];               // <att, xl_n> per head
__device__ float g_w[H_ * NN_];               // <att, xr_n> per head

// ---------------- cp.async helpers ------------------------------------------
__device__ __forceinline__ unsigned s2u(const void* p)
{
    return (unsigned)__cvta_generic_to_shared(p);
}
__device__ __forceinline__ void cp8(unsigned dst, const void* src, bool ok)
{
    int sz = ok ? 8 : 0;
    asm volatile("cp.async.ca.shared.global [%0], [%1], 8, %2;"
                 :: "r"(dst), "l"(src), "r"(sz));
}
__device__ __forceinline__ void cp16(unsigned dst, const void* src, bool ok)
{
    int sz = ok ? 16 : 0;
    asm volatile("cp.async.cg.shared.global [%0], [%1], 16, %2;"
                 :: "r"(dst), "l"(src), "r"(sz));
}
__device__ __forceinline__ void cp_commit()
{
    asm volatile("cp.async.commit_group;");
}
__device__ __forceinline__ void cp_wait0()
{
    asm volatile("cp.async.wait_group 0;" ::: "memory");
}

// ---------------- u/w rank-1 terms: u[h,n]=<att_h, xl[n,h,:]>, w likewise ---
__global__ __launch_bounds__(128) void uw_kernel(const float* __restrict__ xl,
                                                 const float* __restrict__ xr,
                                                 const float* __restrict__ att_l,
                                                 float* __restrict__ u,
                                                 float* __restrict__ w)
{
    int n = blockIdx.x;
    int h = threadIdx.x >> 5, lane = threadIdx.x & 31;
    const float4* xlp = (const float4*)&xl[(size_t)n * HC_ + h * C_];
    const float4* xrp = (const float4*)&xr[(size_t)n * HC_ + h * C_];
    const float4* ap  = (const float4*)&att_l[h * C_];
    float su = 0.f, sw = 0.f;
#pragma unroll
    for (int i = 0; i < 2; i++) {
        float4 a = ap[lane + 32 * i];
        float4 vl = xlp[lane + 32 * i];
        float4 vr = xrp[lane + 32 * i];
        su += a.x * vl.x + a.y * vl.y + a.z * vl.z + a.w * vl.w;
        sw += a.x * vr.x + a.y * vr.y + a.z * vr.z + a.w * vr.w;
    }
#pragma unroll
    for (int o = 16; o; o >>= 1) {
        su += __shfl_xor_sync(0xffffffffu, su, o);
        sw += __shfl_xor_sync(0xffffffffu, sw, o);
    }
    if (lane == 0) {
        u[h * NN_ + n] = su;
        w[h * NN_ + n] = sw;
    }
}

// ---------------- fused logits + softmax + aggregation ----------------------
// grid (43 d-tiles, 8 bh), block 128 = 4 warps. (R10 proven config)
// warp = (d-pair ty, s-half hf): 2 d-rows x 3 s-bands.
struct AttnSmem {
    union {
        struct {
            float XLs[2][6][32][38];
            float XR[4][256];
            float A4[256];
        } pa;
        struct {
            float Xs[2][32][260];
        } pb;
    } u;
    float AL[4][193];
    float MX[4][2];
    float SS[4][2];
};
#define ATTN_SMEM_BYTES sizeof(AttnSmem)

__global__ __launch_bounds__(128) void attn_agg_kernel(const float* __restrict__ xl,
                                                       const float* __restrict__ xr,
                                                       const float* __restrict__ att_l,
                                                       const float* __restrict__ u,
                                                       const float* __restrict__ w,
                                                       float* __restrict__ agg)
{
    extern __shared__ __align__(16) char smem_raw[];
    AttnSmem* sm = (AttnSmem*)smem_raw;

    int tid = threadIdx.x;
    int lane = tid & 31;
    int wid = tid >> 5;
    int ty = wid >> 1;            // d-pair 0..1
    int hf = wid & 1;             // s-half: bands {0,1,2} or {3,4,5}
    int dt = blockIdx.x, bh = blockIdx.y;
    int b = bh >> 2, h = bh & 3;
    int d0 = dt * 4 + ty * 2;
    int d1 = d0 + 1;
    bool dok0 = d0 < N_, dok1 = d1 < N_;

    const float* xlh = xl + (size_t)b * N_ * HC_ + h * C_;

    // ---- stage chunk 0 of XLs (async), then XR + A4 (sync LDG, once) ----
#pragma unroll
    for (int i = 0; i < 24; i++) {
        int f = tid + 128 * i;          // 3072 float2
        int st = f >> 9;
        int rem = f & 511;
        int row = rem >> 4;
        int cc = (rem & 15) * 2;
        int s = st * 32 + row;
        bool ok = s < N_;
        cp8(s2u(&sm->u.pa.XLs[0][st][row][cc]),
            &xlh[(size_t)(ok ? s : 0) * HC_ + cc], ok);
    }
    cp_commit();
#pragma unroll
    for (int i = 0; i < 4; i++) {
        int f = tid + 128 * i;          // 512 float2 for XR[4][256]
        int row = f >> 7;
        int cc = (f & 127) * 2;
        int dr = dt * 4 + row;
        float2 v = make_float2(0.f, 0.f);
        if (dr < N_) v = *(const float2*)&xr[(size_t)(b * N_ + dr) * HC_ + h * C_ + cc];
        *(float2*)&sm->u.pa.XR[row][cc] = v;
    }
    {
        float2 a = *(const float2*)&att_l[h * C_ + tid * 2];
        sm->u.pa.A4[tid * 2]     = 0.4f * a.x;
        sm->u.pa.A4[tid * 2 + 1] = 0.4f * a.y;
    }

    ull acc0[3], acc1[3];
#pragma unroll
    for (int j = 0; j < 3; j++) { acc0[j] = 0ull; acc1[j] = 0ull; }
    const ull msk = 0x7FFFFFFF7FFFFFFFULL;

    // ---------------- Phase A: pipelined over 8 ck-chunks ----------------
#pragma unroll 1
    for (int ch = 0; ch < 8; ch++) {
        cp_wait0();
        __syncthreads();
        if (ch + 1 < 8) {
            int nb = (ch + 1) & 1;
            int ckn = (ch + 1) * 32;
#pragma unroll
            for (int i = 0; i < 24; i++) {
                int f = tid + 128 * i;
                int st = f >> 9;
                int rem = f & 511;
                int row = rem >> 4;
                int cc = (rem & 15) * 2;
                int s = st * 32 + row;
                bool ok = s < N_;
                cp8(s2u(&sm->u.pa.XLs[nb][st][row][cc]),
                    &xlh[(size_t)(ok ? s : 0) * HC_ + ckn + cc], ok);
            }
            cp_commit();
        }
        int bf = ch & 1;
        int ck = ch * 32;
#pragma unroll
        for (int c2 = 0; c2 < 16; c2++) {
            ull r0 = *(const ull*)&sm->u.pa.XR[ty * 2][ck + c2 * 2];
            ull r1 = *(const ull*)&sm->u.pa.XR[ty * 2 + 1][ck + c2 * 2];
            ull a4 = *(const ull*)&sm->u.pa.A4[ck + c2 * 2];
#pragma unroll
            for (int j = 0; j < 3; j++) {
                ull l = *(const ull*)&sm->u.pa.XLs[bf][hf * 3 + j][lane][c2 * 2];
                ull s0, m0, s1, m1;
                asm("add.rn.f32x2 %0, %1, %2;" : "=l"(s0) : "l"(l), "l"(r0));
                asm("add.rn.f32x2 %0, %1, %2;" : "=l"(s1) : "l"(l), "l"(r1));
                asm("and.b64 %0, %1, %2;"      : "=l"(m0) : "l"(s0), "l"(msk));
                asm("and.b64 %0, %1, %2;"      : "=l"(m1) : "l"(s1), "l"(msk));
                asm("fma.rn.f32x2 %0, %1, %2, %0;" : "+l"(acc0[j]) : "l"(m0), "l"(a4));
                asm("fma.rn.f32x2 %0, %1, %2, %0;" : "+l"(acc1[j]) : "l"(m1), "l"(a4));
            }
        }
        __syncthreads();
    }

    // ---- prefetch phase-B chunk 0 now; softmax hides its latency ----
#pragma unroll
    for (int i = 0; i < 16; i++) {
        int f = tid + 128 * i;          // 2048 float4
        int row = f >> 6, col4 = f & 63;
        int s = row;
        bool ok = s < N_;
        cp16(s2u(&sm->u.pb.Xs[0][row][col4 * 4]),
             &xlh[(size_t)(ok ? s : 0) * HC_ + col4 * 4], ok);
    }
    cp_commit();

    // ---------------- softmax (2 d-rows per warp, 2-warp combine) --------
    float w_d0 = dok0 ? w[h * NN_ + b * N_ + d0] : 0.f;
    float w_d1 = dok1 ? w[h * NN_ + b * N_ + d1] : 0.f;
    float lg0[3], lg1[3];
    float mx0 = -1e30f, mx1 = -1e30f;
#pragma unroll
    for (int j = 0; j < 3; j++) {
        int s = (hf * 3 + j) * 32 + lane;
        float uv = (s < N_) ? u[h * NN_ + b * N_ + s] : 0.f;
        {
            ull a = acc0[j];
            float lo = __uint_as_float((unsigned)(a & 0xffffffffu));
            float hi = __uint_as_float((unsigned)(a >> 32));
            float v = 0.6f * (uv + w_d0) + lo + hi;
            if (s >= N_ || s == d0) v = -1e30f;
            lg0[j] = v;
            mx0 = fmaxf(mx0, v);
        }
        {
            ull a = acc1[j];
            float lo = __uint_as_float((unsigned)(a & 0xffffffffu));
            float hi = __uint_as_float((unsigned)(a >> 32));
            float v = 0.6f * (uv + w_d1) + lo + hi;
            if (s >= N_ || s == d1) v = -1e30f;
            lg1[j] = v;
            mx1 = fmaxf(mx1, v);
        }
    }
#pragma unroll
    for (int o = 16; o; o >>= 1) {
        mx0 = fmaxf(mx0, __shfl_xor_sync(0xffffffffu, mx0, o));
        mx1 = fmaxf(mx1, __shfl_xor_sync(0xffffffffu, mx1, o));
    }
    if (lane == 0) {
        sm->MX[ty * 2][hf]     = mx0;
        sm->MX[ty * 2 + 1][hf] = mx1;
    }
    __syncthreads();
    float gmx0 = fmaxf(sm->MX[ty * 2][0],     sm->MX[ty * 2][1]);
    float gmx1 = fmaxf(sm->MX[ty * 2 + 1][0], sm->MX[ty * 2 + 1][1]);
    float sum0 = 0.f, sum1 = 0.f;
#pragma unroll
    for (int j = 0; j < 3; j++) {
        float e0 = __expf(lg0[j] - gmx0);
        float e1 = __expf(lg1[j] - gmx1);
        lg0[j] = e0; lg1[j] = e1;
        sum0 += e0; sum1 += e1;
    }
#pragma unroll
    for (int o = 16; o; o >>= 1) {
        sum0 += __shfl_xor_sync(0xffffffffu, sum0, o);
        sum1 += __shfl_xor_sync(0xffffffffu, sum1, o);
    }
    if (lane == 0) {
        sm->SS[ty * 2][hf]     = sum0;
        sm->SS[ty * 2 + 1][hf] = sum1;
    }
    __syncthreads();
    float inv0 = 1.f / (sm->SS[ty * 2][0]     + sm->SS[ty * 2][1]     + 1e-16f);
    float inv1 = 1.f / (sm->SS[ty * 2 + 1][0] + sm->SS[ty * 2 + 1][1] + 1e-16f);
#pragma unroll
    for (int j = 0; j < 3; j++) {
        sm->AL[ty * 2][(hf * 3 + j) * 32 + lane]     = lg0[j] * inv0;
        sm->AL[ty * 2 + 1][(hf * 3 + j) * 32 + lane] = lg1[j] * inv1;
    }
    // AL write -> read ordering provided by the __syncthreads at phase-B loop head

    // ---------------- Phase B: warp = (d-pair, c-half) -------------------
    float4 accA = make_float4(0.f, 0.f, 0.f, 0.f);   // d0
    float4 accB = make_float4(0.f, 0.f, 0.f, 0.f);   // d1
    int cb = hf * 128 + lane * 4;
#pragma unroll 1
    for (int ch = 0; ch < 6; ch++) {
        cp_wait0();
        __syncthreads();
        if (ch + 1 < 6) {
            int nb = (ch + 1) & 1;
            int skn = (ch + 1) * 32;
#pragma unroll
            for (int i = 0; i < 16; i++) {
                int f = tid + 128 * i;
                int row = f >> 6, col4 = f & 63;
                int s = skn + row;
                bool ok = s < N_;
                cp16(s2u(&sm->u.pb.Xs[nb][row][col4 * 4]),
                     &xlh[(size_t)(ok ? s : 0) * HC_ + col4 * 4], ok);
            }
            cp_commit();
        }
        int bf = ch & 1;
        int sk = ch * 32;
#pragma unroll
        for (int k = 0; k < 32; k++) {
            float av0 = sm->AL[ty * 2][sk + k];
            float av1 = sm->AL[ty * 2 + 1][sk + k];
            float4 x = *(const float4*)&sm->u.pb.Xs[bf][k][cb];
            accA.x = fmaf(av0, x.x, accA.x); accA.y = fmaf(av0, x.y, accA.y);
            accA.z = fmaf(av0, x.z, accA.z); accA.w = fmaf(av0, x.w, accA.w);
            accB.x = fmaf(av1, x.x, accB.x); accB.y = fmaf(av1, x.y, accB.y);
            accB.z = fmaf(av1, x.z, accB.z); accB.w = fmaf(av1, x.w, accB.w);
        }
        __syncthreads();
    }

    if (dok0)
        *(float4*)&agg[((size_t)bh * N_ + d0) * C_ + cb] = accA;
    if (dok1)
        *(float4*)&agg[((size_t)bh * N_ + d1) * C_ + cb] = accB;
}

// ---------------- fused xl/xr GEMM, cp.async double-buffered ----------------
__global__ __launch_bounds__(256) void gemm_dual(const float* __restrict__ A,
                                                 const float* __restrict__ B1,
                                                 const float* __restrict__ c1,
                                                 float* __restrict__ o1,
                                                 const float* __restrict__ B2,
                                                 const float* __restrict__ c2p,
                                                 float* __restrict__ o2,
                                                 int M, int K)
{
    __shared__ __align__(16) float As[2][64][36];
    __shared__ __align__(16) float Bs[2][32][36];

    const float* Bm;
    const float* bias;
    float* out;
    int n0;
    if (blockIdx.x < 32) { Bm = B1; bias = c1;  out = o1; n0 = blockIdx.x * 32; }
    else                 { Bm = B2; bias = c2p; out = o2; n0 = (blockIdx.x - 32) * 32; }

    int tid = threadIdx.x;
    int tx = tid & 15, ty = tid >> 4;
    int m0 = blockIdx.y * 64;

    int a_row = tid >> 2, a_c4a = (tid & 3) * 2;
    int b_row = tid >> 3, b_c4 = tid & 7;

    {
        bool okA = (m0 + a_row) < M;
        const float* srcA = &A[(size_t)(m0 + (okA ? a_row : 0)) * K + a_c4a * 4];
        cp16(s2u(&As[0][a_row][a_c4a * 4]), srcA, okA);
        cp16(s2u(&As[0][a_row][(a_c4a + 1) * 4]), srcA + 4, okA);
        cp16(s2u(&Bs[0][b_row][b_c4 * 4]),
             &Bm[(size_t)b_row * HC_ + n0 + b_c4 * 4], true);
    }
    cp_commit();

    float acc[4][2];
#pragma unroll
    for (int i = 0; i < 4; i++) { acc[i][0] = 0.f; acc[i][1] = 0.f; }

    int nch = K / 32;
#pragma unroll 1
    for (int ch = 0; ch < nch; ch++) {
        cp_wait0();
        __syncthreads();
        if (ch + 1 < nch) {
            int nb = (ch + 1) & 1;
            int kkn = (ch + 1) * 32;
            bool okA = (m0 + a_row) < M;
            const float* srcA = &A[(size_t)(m0 + (okA ? a_row : 0)) * K + kkn + a_c4a * 4];
            cp16(s2u(&As[nb][a_row][a_c4a * 4]), srcA, okA);
            cp16(s2u(&As[nb][a_row][(a_c4a + 1) * 4]), srcA + 4, okA);
            cp16(s2u(&Bs[nb][b_row][b_c4 * 4]),
                 &Bm[(size_t)(kkn + b_row) * HC_ + n0 + b_c4 * 4], true);
            cp_commit();
        }
        int bf = ch & 1;
#pragma unroll
        for (int k = 0; k < 32; k++) {
            float a0 = As[bf][ty * 4 + 0][k];
            float a1 = As[bf][ty * 4 + 1][k];
            float a2 = As[bf][ty * 4 + 2][k];
            float a3 = As[bf][ty * 4 + 3][k];
            float2 bv = *(const float2*)&Bs[bf][k][tx * 2];
            acc[0][0] = fmaf(a0, bv.x, acc[0][0]); acc[0][1] = fmaf(a0, bv.y, acc[0][1]);
            acc[1][0] = fmaf(a1, bv.x, acc[1][0]); acc[1][1] = fmaf(a1, bv.y, acc[1][1]);
            acc[2][0] = fmaf(a2, bv.x, acc[2][0]); acc[2][1] = fmaf(a2, bv.y, acc[2][1]);
            acc[3][0] = fmaf(a3, bv.x, acc[3][0]); acc[3][1] = fmaf(a3, bv.y, acc[3][1]);
        }
        __syncthreads();
    }

    float b0 = bias[n0 + tx * 2], b1 = bias[n0 + tx * 2 + 1];
#pragma unroll
    for (int i = 0; i < 4; i++) {
        int r = m0 + ty * 4 + i;
        if (r < M) {
            out[(size_t)r * HC_ + n0 + tx * 2]     = acc[i][0] + b0;
            out[(size_t)r * HC_ + n0 + tx * 2 + 1] = acc[i][1] + b1;
        }
    }
}

// ---------------- generic 32x32 GEMM, cp.async double-buffered --------------
// mode: 1 relu, 2 residual: out = resid + acc + bias
__global__ void gemm_kernel(const float* __restrict__ A,
                            const float* __restrict__ Bm,
                            const float* __restrict__ bias,
                            const float* __restrict__ resid,
                            float* __restrict__ out,
                            int M, int N, int K, int mode)
{
    __shared__ __align__(16) float As[2][32][36];
    __shared__ __align__(16) float Bs[2][32][36];
    int tid = threadIdx.x;
    int tx = tid & 15, ty = tid >> 4;
    int m0 = blockIdx.y * 32;
    int n0 = blockIdx.x * 32;
    int lr = tid >> 3, lc4 = tid & 7;
    float a00 = 0.f, a01 = 0.f, a10 = 0.f, a11 = 0.f;

    {
        bool okA = (m0 + lr) < M;
        cp16(s2u(&As[0][lr][lc4 * 4]),
             &A[(size_t)(m0 + (okA ? lr : 0)) * K + lc4 * 4], okA);
        cp16(s2u(&Bs[0][lr][lc4 * 4]),
             &Bm[(size_t)lr * N + n0 + lc4 * 4], true);
    }
    cp_commit();

    int nch = K / 32;
#pragma unroll 1
    for (int ch = 0; ch < nch; ch++) {
        cp_wait0();
        __syncthreads();
        if (ch + 1 < nch) {
            int nb = (ch + 1) & 1;
            int kkn = (ch + 1) * 32;
            bool okA = (m0 + lr) < M;
            cp16(s2u(&As[nb][lr][lc4 * 4]),
                 &A[(size_t)(m0 + (okA ? lr : 0)) * K + kkn + lc4 * 4], okA);
            cp16(s2u(&Bs[nb][lr][lc4 * 4]),
                 &Bm[(size_t)(kkn + lr) * N + n0 + lc4 * 4], true);
            cp_commit();
        }
        int bf = ch & 1;
#pragma unroll
        for (int k = 0; k < 32; k++) {
            float av0 = As[bf][ty][k],      av1 = As[bf][ty + 16][k];
            float bv0 = Bs[bf][k][tx],      bv1 = Bs[bf][k][tx + 16];
            a00 = fmaf(av0, bv0, a00);  a01 = fmaf(av0, bv1, a01);
            a10 = fmaf(av1, bv0, a10);  a11 = fmaf(av1, bv1, a11);
        }
        __syncthreads();
    }

    int r0 = m0 + ty, r1 = m0 + ty + 16;
    int c0 = n0 + tx, c1 = n0 + tx + 16;
    float b0 = bias[c0], b1 = bias[c1];
    if (mode == 1) {
        if (r0 < M) { out[r0 * N + c0] = fmaxf(a00 + b0, 0.f); out[r0 * N + c1] = fmaxf(a01 + b1, 0.f); }
        if (r1 < M) { out[r1 * N + c0] = fmaxf(a10 + b0, 0.f); out[r1 * N + c1] = fmaxf(a11 + b1, 0.f); }
    } else {
        if (r0 < M) {
            out[r0 * N + c0] = resid[r0 * N + c0] + a00 + b0;
            out[r0 * N + c1] = resid[r0 * N + c1] + a01 + b1;
        }
        if (r1 < M) {
            out[r1 * N + c0] = resid[r1 * N + c0] + a10 + b0;
            out[r1 * N + c1] = resid[r1 * N + c1] + a11 + b1;
        }
    }
}

// ---------------- head-mean + bias + layernorm: warp-per-row, no barriers ---
__global__ __launch_bounds__(128) void ln_kernel(const float* __restrict__ agg,
                                                 const float* __restrict__ bias_l,
                                                 const float* __restrict__ g,
                                                 const float* __restrict__ bt,
                                                 float* __restrict__ out)
{
    int lane = threadIdx.x & 31;
    int wrp = threadIdx.x >> 5;
    int n = blockIdx.x * 4 + wrp;
    if (n >= NN_) return;
    int b = (n >= N_) ? 1 : 0;
    int d = n - b * N_;

    // two float4 per lane: c = lane*4 and lane*4+128
    float4 v0 = make_float4(0.f, 0.f, 0.f, 0.f);
    float4 v1 = make_float4(0.f, 0.f, 0.f, 0.f);
#pragma unroll
    for (int h = 0; h < H_; h++) {
        const float* base = &agg[((size_t)(b * H_ + h) * N_ + d) * C_];
        float4 t0 = *(const float4*)&base[lane * 4];
        float4 t1 = *(const float4*)&base[lane * 4 + 128];
        v0.x += t0.x; v0.y += t0.y; v0.z += t0.z; v0.w += t0.w;
        v1.x += t1.x; v1.y += t1.y; v1.z += t1.z; v1.w += t1.w;
    }
    float4 bb0 = *(const float4*)&bias_l[lane * 4];
    float4 bb1 = *(const float4*)&bias_l[lane * 4 + 128];
    v0.x = 0.25f * v0.x + bb0.x; v0.y = 0.25f * v0.y + bb0.y;
    v0.z = 0.25f * v0.z + bb0.z; v0.w = 0.25f * v0.w + bb0.w;
    v1.x = 0.25f * v1.x + bb1.x; v1.y = 0.25f * v1.y + bb1.y;
    v1.z = 0.25f * v1.z + bb1.z; v1.w = 0.25f * v1.w + bb1.w;

    float s = v0.x + v0.y + v0.z + v0.w + v1.x + v1.y + v1.z + v1.w;
#pragma unroll
    for (int o = 16; o; o >>= 1) s += __shfl_xor_sync(0xffffffffu, s, o);
    float mu = s * (1.f / C_);

    float4 e0 = make_float4(v0.x - mu, v0.y - mu, v0.z - mu, v0.w - mu);
    float4 e1 = make_float4(v1.x - mu, v1.y - mu, v1.z - mu, v1.w - mu);
    float s2 = e0.x * e0.x + e0.y * e0.y + e0.z * e0.z + e0.w * e0.w
             + e1.x * e1.x + e1.y * e1.y + e1.z * e1.z + e1.w * e1.w;
#pragma unroll
    for (int o = 16; o; o >>= 1) s2 += __shfl_xor_sync(0xffffffffu, s2, o);
    float rstd = rsqrtf(s2 * (1.f / C_) + 1e-5f);

    float4 g0 = *(const float4*)&g[lane * 4];
    float4 g1 = *(const float4*)&g[lane * 4 + 128];
    float4 t0 = *(const float4*)&bt[lane * 4];
    float4 t1 = *(const float4*)&bt[lane * 4 + 128];
    float4 o0, o1;
    o0.x = e0.x * rstd * g0.x + t0.x; o0.y = e0.y * rstd * g0.y + t0.y;
    o0.z = e0.z * rstd * g0.z + t0.z; o0.w = e0.w * rstd * g0.w + t0.w;
    o1.x = e1.x * rstd * g1.x + t1.x; o1.y = e1.y * rstd * g1.y + t1.y;
    o1.z = e1.z * rstd * g1.z + t1.z; o1.w = e1.w * rstd * g1.w + t1.w;
    *(float4*)&out[(size_t)n * C_ + lane * 4]       = o0;
    *(float4*)&out[(size_t)n * C_ + lane * 4 + 128] = o1;
}

// ---------------- final mean pool per graph ----------------------------------
__global__ void pool_kernel(const float* __restrict__ x, float* __restrict__ out)
{
    int b = blockIdx.x, t = threadIdx.x;
    float s = 0.f;
#pragma unroll 13
    for (int d = 0; d < N_; d++) s += x[(b * N_ + d) * C_ + t];
    out[b * C_ + t] = s * (1.f / N_);
}

// ---------------- host launcher -----------------------------------------------
extern "C" void kernel_launch(void* const* d_in, const int* in_sizes, int n_in,
                              void* d_out, int out_size)
{
    const float* x    = (const float*)d_in[0];
    const float* Wl   = (const float*)d_in[1];
    const float* bl   = (const float*)d_in[2];
    const float* Wr   = (const float*)d_in[3];
    const float* br   = (const float*)d_in[4];
    const float* att  = (const float*)d_in[5];
    const float* bias = (const float*)d_in[6];
    const float* lng  = (const float*)d_in[7];
    const float* lnb  = (const float*)d_in[8];
    const float* W1   = (const float*)d_in[9];
    const float* b1   = (const float*)d_in[10];
    const float* W2   = (const float*)d_in[11];
    const float* b2   = (const float*)d_in[12];

    float *bx, *bxl, *bxr, *bag, *bh, *bm, *bu, *bw;
    cudaGetSymbolAddress((void**)&bx,  g_x);
    cudaGetSymbolAddress((void**)&bxl, g_xl);
    cudaGetSymbolAddress((void**)&bxr, g_xr);
    cudaGetSymbolAddress((void**)&bag, g_agg);
    cudaGetSymbolAddress((void**)&bh,  g_h);
    cudaGetSymbolAddress((void**)&bm,  g_m);
    cudaGetSymbolAddress((void**)&bu,  g_u);
    cudaGetSymbolAddress((void**)&bw,  g_w);

    static int attr_done = 0;
    if (!attr_done) {
        cudaFuncSetAttribute(attn_agg_kernel,
                             cudaFuncAttributeMaxDynamicSharedMemorySize,
                             (int)ATTN_SMEM_BYTES);
        attr_done = 1;
    }

    for (int l = 0; l < L_; l++) {
        const float* xin = (l == 0) ? x : bx;
        gemm_dual<<<dim3(64, 6), 256>>>(xin,
                                        Wl + l * C_ * HC_, bl + l * HC_, bxl,
                                        Wr + l * C_ * HC_, br + l * HC_, bxr,
                                        NN_, C_);
        uw_kernel<<<NN_, 128>>>(bxl, bxr, att + l * H_ * C_, bu, bw);
        attn_agg_kernel<<<dim3(43, 8), 128, ATTN_SMEM_BYTES>>>(
            bxl, bxr, att + l * H_ * C_, bu, bw, bag);
        ln_kernel<<<85, 128>>>(bag, bias + l * C_, lng + l * C_, lnb + l * C_, bh);
        gemm_kernel<<<dim3(16, 11), 256>>>(bh, W1 + l * C_ * 2 * C_, b1 + l * 2 * C_,
                                           nullptr, bm, NN_, 2 * C_, C_, 1);
        gemm_kernel<<<dim3(8, 11), 256>>>(bm, W2 + l * 2 * C_ * C_, b2 + l * C_,
                                          xin, bx, NN_, C_, 2 * C_, 2);
    }

    pool_kernel<<<B_, 256>>>(bx, (float*)d_out);
}

// round 13
// speedup vs baseline: 1.1694x; 1.0002x over previous
#include <cuda_runtime.h>

#define B_   2
#define N_   169
#define NN_  338
#define C_   256
#define H_   4
#define HC_  1024
#define L_   3

typedef unsigned long long ull;

// ---------------- scratch (device globals) ---------------------------------
__device__ float g_x[NN_ * C_];               // running node features
__device__ float g_xl[NN_ * HC_];             // x @ Wl + bl
__device__ float g_xr[NN_ * HC_];             // x @ Wr + br
__device__ float g_agg[B_ * H_ * N_ * C_];    // per-head aggregation partials
__device__ float g_h[NN_ * C_];               // post layernorm
__device__ float g_m[NN_ * 2 * C_];           // mlp hidden
__device__ float g_u[H_ * NN_];               // <att, xl_n> per head
__device__ float g_w[H_ * NN_];               // <att, xr_n> per head

// ---------------- cp.async helpers ------------------------------------------
__device__ __forceinline__ unsigned s2u(const void* p)
{
    return (unsigned)__cvta_generic_to_shared(p);
}
__device__ __forceinline__ void cp8(unsigned dst, const void* src, bool ok)
{
    int sz = ok ? 8 : 0;
    asm volatile("cp.async.ca.shared.global [%0], [%1], 8, %2;"
                 :: "r"(dst), "l"(src), "r"(sz));
}
__device__ __forceinline__ void cp16(unsigned dst, const void* src, bool ok)
{
    int sz = ok ? 16 : 0;
    asm volatile("cp.async.cg.shared.global [%0], [%1], 16, %2;"
                 :: "r"(dst), "l"(src), "r"(sz));
}
__device__ __forceinline__ void cp_commit()
{
    asm volatile("cp.async.commit_group;");
}
__device__ __forceinline__ void cp_wait0()
{
    asm volatile("cp.async.wait_group 0;" ::: "memory");
}

// ---------------- u/w rank-1 terms: u[h,n]=<att_h, xl[n,h,:]>, w likewise ---
__global__ __launch_bounds__(128) void uw_kernel(const float* __restrict__ xl,
                                                 const float* __restrict__ xr,
                                                 const float* __restrict__ att_l,
                                                 float* __restrict__ u,
                                                 float* __restrict__ w)
{
    int n = blockIdx.x;
    int h = threadIdx.x >> 5, lane = threadIdx.x & 31;
    const float4* xlp = (const float4*)&xl[(size_t)n * HC_ + h * C_];
    const float4* xrp = (const float4*)&xr[(size_t)n * HC_ + h * C_];
    const float4* ap  = (const float4*)&att_l[h * C_];
    float su = 0.f, sw = 0.f;
#pragma unroll
    for (int i = 0; i < 2; i++) {
        float4 a = ap[lane + 32 * i];
        float4 vl = xlp[lane + 32 * i];
        float4 vr = xrp[lane + 32 * i];
        su += a.x * vl.x + a.y * vl.y + a.z * vl.z + a.w * vl.w;
        sw += a.x * vr.x + a.y * vr.y + a.z * vr.z + a.w * vr.w;
    }
#pragma unroll
    for (int o = 16; o; o >>= 1) {
        su += __shfl_xor_sync(0xffffffffu, su, o);
        sw += __shfl_xor_sync(0xffffffffu, sw, o);
    }
    if (lane == 0) {
        u[h * NN_ + n] = su;
        w[h * NN_ + n] = sw;
    }
}

// ---------------- fused logits + softmax + aggregation ----------------------
// grid (43 d-tiles, 8 bh), block 128 = 4 warps. (R10 proven config)
struct AttnSmem {
    union {
        struct {
            float XLs[2][6][32][38];
            float XR[4][256];
            float A4[256];
        } pa;
        struct {
            float Xs[2][32][260];
        } pb;
    } u;
    float AL[4][193];
    float MX[4][2];
    float SS[4][2];
};
#define ATTN_SMEM_BYTES sizeof(AttnSmem)

__global__ __launch_bounds__(128) void attn_agg_kernel(const float* __restrict__ xl,
                                                       const float* __restrict__ xr,
                                                       const float* __restrict__ att_l,
                                                       const float* __restrict__ u,
                                                       const float* __restrict__ w,
                                                       float* __restrict__ agg)
{
    extern __shared__ __align__(16) char smem_raw[];
    AttnSmem* sm = (AttnSmem*)smem_raw;

    int tid = threadIdx.x;
    int lane = tid & 31;
    int wid = tid >> 5;
    int ty = wid >> 1;
    int hf = wid & 1;
    int dt = blockIdx.x, bh = blockIdx.y;
    int b = bh >> 2, h = bh & 3;
    int d0 = dt * 4 + ty * 2;
    int d1 = d0 + 1;
    bool dok0 = d0 < N_, dok1 = d1 < N_;

    const float* xlh = xl + (size_t)b * N_ * HC_ + h * C_;

#pragma unroll
    for (int i = 0; i < 24; i++) {
        int f = tid + 128 * i;
        int st = f >> 9;
        int rem = f & 511;
        int row = rem >> 4;
        int cc = (rem & 15) * 2;
        int s = st * 32 + row;
        bool ok = s < N_;
        cp8(s2u(&sm->u.pa.XLs[0][st][row][cc]),
            &xlh[(size_t)(ok ? s : 0) * HC_ + cc], ok);
    }
    cp_commit();
#pragma unroll
    for (int i = 0; i < 4; i++) {
        int f = tid + 128 * i;
        int row = f >> 7;
        int cc = (f & 127) * 2;
        int dr = dt * 4 + row;
        float2 v = make_float2(0.f, 0.f);
        if (dr < N_) v = *(const float2*)&xr[(size_t)(b * N_ + dr) * HC_ + h * C_ + cc];
        *(float2*)&sm->u.pa.XR[row][cc] = v;
    }
    {
        float2 a = *(const float2*)&att_l[h * C_ + tid * 2];
        sm->u.pa.A4[tid * 2]     = 0.4f * a.x;
        sm->u.pa.A4[tid * 2 + 1] = 0.4f * a.y;
    }

    ull acc0[3], acc1[3];
#pragma unroll
    for (int j = 0; j < 3; j++) { acc0[j] = 0ull; acc1[j] = 0ull; }
    const ull msk = 0x7FFFFFFF7FFFFFFFULL;

#pragma unroll 1
    for (int ch = 0; ch < 8; ch++) {
        cp_wait0();
        __syncthreads();
        if (ch + 1 < 8) {
            int nb = (ch + 1) & 1;
            int ckn = (ch + 1) * 32;
#pragma unroll
            for (int i = 0; i < 24; i++) {
                int f = tid + 128 * i;
                int st = f >> 9;
                int rem = f & 511;
                int row = rem >> 4;
                int cc = (rem & 15) * 2;
                int s = st * 32 + row;
                bool ok = s < N_;
                cp8(s2u(&sm->u.pa.XLs[nb][st][row][cc]),
                    &xlh[(size_t)(ok ? s : 0) * HC_ + ckn + cc], ok);
            }
            cp_commit();
        }
        int bf = ch & 1;
        int ck = ch * 32;
#pragma unroll
        for (int c2 = 0; c2 < 16; c2++) {
            ull r0 = *(const ull*)&sm->u.pa.XR[ty * 2][ck + c2 * 2];
            ull r1 = *(const ull*)&sm->u.pa.XR[ty * 2 + 1][ck + c2 * 2];
            ull a4 = *(const ull*)&sm->u.pa.A4[ck + c2 * 2];
#pragma unroll
            for (int j = 0; j < 3; j++) {
                ull l = *(const ull*)&sm->u.pa.XLs[bf][hf * 3 + j][lane][c2 * 2];
                ull s0, m0, s1, m1;
                asm("add.rn.f32x2 %0, %1, %2;" : "=l"(s0) : "l"(l), "l"(r0));
                asm("add.rn.f32x2 %0, %1, %2;" : "=l"(s1) : "l"(l), "l"(r1));
                asm("and.b64 %0, %1, %2;"      : "=l"(m0) : "l"(s0), "l"(msk));
                asm("and.b64 %0, %1, %2;"      : "=l"(m1) : "l"(s1), "l"(msk));
                asm("fma.rn.f32x2 %0, %1, %2, %0;" : "+l"(acc0[j]) : "l"(m0), "l"(a4));
                asm("fma.rn.f32x2 %0, %1, %2, %0;" : "+l"(acc1[j]) : "l"(m1), "l"(a4));
            }
        }
        __syncthreads();
    }

#pragma unroll
    for (int i = 0; i < 16; i++) {
        int f = tid + 128 * i;
        int row = f >> 6, col4 = f & 63;
        int s = row;
        bool ok = s < N_;
        cp16(s2u(&sm->u.pb.Xs[0][row][col4 * 4]),
             &xlh[(size_t)(ok ? s : 0) * HC_ + col4 * 4], ok);
    }
    cp_commit();

    float w_d0 = dok0 ? w[h * NN_ + b * N_ + d0] : 0.f;
    float w_d1 = dok1 ? w[h * NN_ + b * N_ + d1] : 0.f;
    float lg0[3], lg1[3];
    float mx0 = -1e30f, mx1 = -1e30f;
#pragma unroll
    for (int j = 0; j < 3; j++) {
        int s = (hf * 3 + j) * 32 + lane;
        float uv = (s < N_) ? u[h * NN_ + b * N_ + s] : 0.f;
        {
            ull a = acc0[j];
            float lo = __uint_as_float((unsigned)(a & 0xffffffffu));
            float hi = __uint_as_float((unsigned)(a >> 32));
            float v = 0.6f * (uv + w_d0) + lo + hi;
            if (s >= N_ || s == d0) v = -1e30f;
            lg0[j] = v;
            mx0 = fmaxf(mx0, v);
        }
        {
            ull a = acc1[j];
            float lo = __uint_as_float((unsigned)(a & 0xffffffffu));
            float hi = __uint_as_float((unsigned)(a >> 32));
            float v = 0.6f * (uv + w_d1) + lo + hi;
            if (s >= N_ || s == d1) v = -1e30f;
            lg1[j] = v;
            mx1 = fmaxf(mx1, v);
        }
    }
#pragma unroll
    for (int o = 16; o; o >>= 1) {
        mx0 = fmaxf(mx0, __shfl_xor_sync(0xffffffffu, mx0, o));
        mx1 = fmaxf(mx1, __shfl_xor_sync(0xffffffffu, mx1, o));
    }
    if (lane == 0) {
        sm->MX[ty * 2][hf]     = mx0;
        sm->MX[ty * 2 + 1][hf] = mx1;
    }
    __syncthreads();
    float gmx0 = fmaxf(sm->MX[ty * 2][0],     sm->MX[ty * 2][1]);
    float gmx1 = fmaxf(sm->MX[ty * 2 + 1][0], sm->MX[ty * 2 + 1][1]);
    float sum0 = 0.f, sum1 = 0.f;
#pragma unroll
    for (int j = 0; j < 3; j++) {
        float e0 = __expf(lg0[j] - gmx0);
        float e1 = __expf(lg1[j] - gmx1);
        lg0[j] = e0; lg1[j] = e1;
        sum0 += e0; sum1 += e1;
    }
#pragma unroll
    for (int o = 16; o; o >>= 1) {
        sum0 += __shfl_xor_sync(0xffffffffu, sum0, o);
        sum1 += __shfl_xor_sync(0xffffffffu, sum1, o);
    }
    if (lane == 0) {
        sm->SS[ty * 2][hf]     = sum0;
        sm->SS[ty * 2 + 1][hf] = sum1;
    }
    __syncthreads();
    float inv0 = 1.f / (sm->SS[ty * 2][0]     + sm->SS[ty * 2][1]     + 1e-16f);
    float inv1 = 1.f / (sm->SS[ty * 2 + 1][0] + sm->SS[ty * 2 + 1][1] + 1e-16f);
#pragma unroll
    for (int j = 0; j < 3; j++) {
        sm->AL[ty * 2][(hf * 3 + j) * 32 + lane]     = lg0[j] * inv0;
        sm->AL[ty * 2 + 1][(hf * 3 + j) * 32 + lane] = lg1[j] * inv1;
    }

    float4 accA = make_float4(0.f, 0.f, 0.f, 0.f);
    float4 accB = make_float4(0.f, 0.f, 0.f, 0.f);
    int cb = hf * 128 + lane * 4;
#pragma unroll 1
    for (int ch = 0; ch < 6; ch++) {
        cp_wait0();
        __syncthreads();
        if (ch + 1 < 6) {
            int nb = (ch + 1) & 1;
            int skn = (ch + 1) * 32;
#pragma unroll
            for (int i = 0; i < 16; i++) {
                int f = tid + 128 * i;
                int row = f >> 6, col4 = f & 63;
                int s = skn + row;
                bool ok = s < N_;
                cp16(s2u(&sm->u.pb.Xs[nb][row][col4 * 4]),
                     &xlh[(size_t)(ok ? s : 0) * HC_ + col4 * 4], ok);
            }
            cp_commit();
        }
        int bf = ch & 1;
        int sk = ch * 32;
#pragma unroll
        for (int k = 0; k < 32; k++) {
            float av0 = sm->AL[ty * 2][sk + k];
            float av1 = sm->AL[ty * 2 + 1][sk + k];
            float4 x = *(const float4*)&sm->u.pb.Xs[bf][k][cb];
            accA.x = fmaf(av0, x.x, accA.x); accA.y = fmaf(av0, x.y, accA.y);
            accA.z = fmaf(av0, x.z, accA.z); accA.w = fmaf(av0, x.w, accA.w);
            accB.x = fmaf(av1, x.x, accB.x); accB.y = fmaf(av1, x.y, accB.y);
            accB.z = fmaf(av1, x.z, accB.z); accB.w = fmaf(av1, x.w, accB.w);
        }
        __syncthreads();
    }

    if (dok0)
        *(float4*)&agg[((size_t)bh * N_ + d0) * C_ + cb] = accA;
    if (dok1)
        *(float4*)&agg[((size_t)bh * N_ + d1) * C_ + cb] = accB;
}

// ---------------- fused xl/xr GEMM: 64x64 tile, 4x4/thread, cp.async --------
// grid (32, 6): bx<16 -> Wl n-tile bx; else Wr n-tile bx-16.
__global__ __launch_bounds__(256) void gemm_dual(const float* __restrict__ A,
                                                 const float* __restrict__ B1,
                                                 const float* __restrict__ c1,
                                                 float* __restrict__ o1,
                                                 const float* __restrict__ B2,
                                                 const float* __restrict__ c2p,
                                                 float* __restrict__ o2,
                                                 int M, int K)
{
    __shared__ __align__(16) float As[2][64][36];   // row-major [row][k]
    __shared__ __align__(16) float Bs[2][32][68];   // [k][n]

    const float* Bm;
    const float* bias;
    float* out;
    int n0;
    if (blockIdx.x < 16) { Bm = B1; bias = c1;  out = o1; n0 = blockIdx.x * 64; }
    else                 { Bm = B2; bias = c2p; out = o2; n0 = (blockIdx.x - 16) * 64; }

    int tid = threadIdx.x;
    int tx = tid & 15, ty = tid >> 4;
    int m0 = blockIdx.y * 64;

    int a_row = tid >> 2, a_c4a = (tid & 3) * 2;    // A: 2 cp16/thread
    int b_row0 = tid >> 4, b_c4 = tid & 15;         // B: rows 0-15 then 16-31

    {
        bool okA = (m0 + a_row) < M;
        const float* srcA = &A[(size_t)(m0 + (okA ? a_row : 0)) * K + a_c4a * 4];
        cp16(s2u(&As[0][a_row][a_c4a * 4]), srcA, okA);
        cp16(s2u(&As[0][a_row][(a_c4a + 1) * 4]), srcA + 4, okA);
        cp16(s2u(&Bs[0][b_row0][b_c4 * 4]),
             &Bm[(size_t)b_row0 * HC_ + n0 + b_c4 * 4], true);
        cp16(s2u(&Bs[0][b_row0 + 16][b_c4 * 4]),
             &Bm[(size_t)(b_row0 + 16) * HC_ + n0 + b_c4 * 4], true);
    }
    cp_commit();

    float acc[4][4];
#pragma unroll
    for (int i = 0; i < 4; i++)
#pragma unroll
        for (int j = 0; j < 4; j++) acc[i][j] = 0.f;

    int nch = K / 32;
#pragma unroll 1
    for (int ch = 0; ch < nch; ch++) {
        cp_wait0();
        __syncthreads();
        if (ch + 1 < nch) {
            int nb = (ch + 1) & 1;
            int kkn = (ch + 1) * 32;
            bool okA = (m0 + a_row) < M;
            const float* srcA = &A[(size_t)(m0 + (okA ? a_row : 0)) * K + kkn + a_c4a * 4];
            cp16(s2u(&As[nb][a_row][a_c4a * 4]), srcA, okA);
            cp16(s2u(&As[nb][a_row][(a_c4a + 1) * 4]), srcA + 4, okA);
            cp16(s2u(&Bs[nb][b_row0][b_c4 * 4]),
                 &Bm[(size_t)(kkn + b_row0) * HC_ + n0 + b_c4 * 4], true);
            cp16(s2u(&Bs[nb][b_row0 + 16][b_c4 * 4]),
                 &Bm[(size_t)(kkn + b_row0 + 16) * HC_ + n0 + b_c4 * 4], true);
            cp_commit();
        }
        int bf = ch & 1;
#pragma unroll
        for (int k = 0; k < 32; k++) {
            float a0 = As[bf][ty * 4 + 0][k];
            float a1 = As[bf][ty * 4 + 1][k];
            float a2 = As[bf][ty * 4 + 2][k];
            float a3 = As[bf][ty * 4 + 3][k];
            float4 bv = *(const float4*)&Bs[bf][k][tx * 4];
            acc[0][0] = fmaf(a0, bv.x, acc[0][0]); acc[0][1] = fmaf(a0, bv.y, acc[0][1]);
            acc[0][2] = fmaf(a0, bv.z, acc[0][2]); acc[0][3] = fmaf(a0, bv.w, acc[0][3]);
            acc[1][0] = fmaf(a1, bv.x, acc[1][0]); acc[1][1] = fmaf(a1, bv.y, acc[1][1]);
            acc[1][2] = fmaf(a1, bv.z, acc[1][2]); acc[1][3] = fmaf(a1, bv.w, acc[1][3]);
            acc[2][0] = fmaf(a2, bv.x, acc[2][0]); acc[2][1] = fmaf(a2, bv.y, acc[2][1]);
            acc[2][2] = fmaf(a2, bv.z, acc[2][2]); acc[2][3] = fmaf(a2, bv.w, acc[2][3]);
            acc[3][0] = fmaf(a3, bv.x, acc[3][0]); acc[3][1] = fmaf(a3, bv.y, acc[3][1]);
            acc[3][2] = fmaf(a3, bv.z, acc[3][2]); acc[3][3] = fmaf(a3, bv.w, acc[3][3]);
        }
        __syncthreads();
    }

    float4 bb = *(const float4*)&bias[n0 + tx * 4];
#pragma unroll
    for (int i = 0; i < 4; i++) {
        int r = m0 + ty * 4 + i;
        if (r < M) {
            float4 o4;
            o4.x = acc[i][0] + bb.x;
            o4.y = acc[i][1] + bb.y;
            o4.z = acc[i][2] + bb.z;
            o4.w = acc[i][3] + bb.w;
            *(float4*)&out[(size_t)r * HC_ + n0 + tx * 4] = o4;
        }
    }
}

// ---------------- generic 32x32 GEMM, cp.async double-buffered --------------
// mode: 1 relu, 2 residual: out = resid + acc + bias
__global__ void gemm_kernel(const float* __restrict__ A,
                            const float* __restrict__ Bm,
                            const float* __restrict__ bias,
                            const float* __restrict__ resid,
                            float* __restrict__ out,
                            int M, int N, int K, int mode)
{
    __shared__ __align__(16) float As[2][32][36];
    __shared__ __align__(16) float Bs[2][32][36];
    int tid = threadIdx.x;
    int tx = tid & 15, ty = tid >> 4;
    int m0 = blockIdx.y * 32;
    int n0 = blockIdx.x * 32;
    int lr = tid >> 3, lc4 = tid & 7;
    float a00 = 0.f, a01 = 0.f, a10 = 0.f, a11 = 0.f;

    {
        bool okA = (m0 + lr) < M;
        cp16(s2u(&As[0][lr][lc4 * 4]),
             &A[(size_t)(m0 + (okA ? lr : 0)) * K + lc4 * 4], okA);
        cp16(s2u(&Bs[0][lr][lc4 * 4]),
             &Bm[(size_t)lr * N + n0 + lc4 * 4], true);
    }
    cp_commit();

    int nch = K / 32;
#pragma unroll 1
    for (int ch = 0; ch < nch; ch++) {
        cp_wait0();
        __syncthreads();
        if (ch + 1 < nch) {
            int nb = (ch + 1) & 1;
            int kkn = (ch + 1) * 32;
            bool okA = (m0 + lr) < M;
            cp16(s2u(&As[nb][lr][lc4 * 4]),
                 &A[(size_t)(m0 + (okA ? lr : 0)) * K + kkn + lc4 * 4], okA);
            cp16(s2u(&Bs[nb][lr][lc4 * 4]),
                 &Bm[(size_t)(kkn + lr) * N + n0 + lc4 * 4], true);
            cp_commit();
        }
        int bf = ch & 1;
#pragma unroll
        for (int k = 0; k < 32; k++) {
            float av0 = As[bf][ty][k],      av1 = As[bf][ty + 16][k];
            float bv0 = Bs[bf][k][tx],      bv1 = Bs[bf][k][tx + 16];
            a00 = fmaf(av0, bv0, a00);  a01 = fmaf(av0, bv1, a01);
            a10 = fmaf(av1, bv0, a10);  a11 = fmaf(av1, bv1, a11);
        }
        __syncthreads();
    }

    int r0 = m0 + ty, r1 = m0 + ty + 16;
    int c0 = n0 + tx, c1 = n0 + tx + 16;
    float b0 = bias[c0], b1 = bias[c1];
    if (mode == 1) {
        if (r0 < M) { out[r0 * N + c0] = fmaxf(a00 + b0, 0.f); out[r0 * N + c1] = fmaxf(a01 + b1, 0.f); }
        if (r1 < M) { out[r1 * N + c0] = fmaxf(a10 + b0, 0.f); out[r1 * N + c1] = fmaxf(a11 + b1, 0.f); }
    } else {
        if (r0 < M) {
            out[r0 * N + c0] = resid[r0 * N + c0] + a00 + b0;
            out[r0 * N + c1] = resid[r0 * N + c1] + a01 + b1;
        }
        if (r1 < M) {
            out[r1 * N + c0] = resid[r1 * N + c0] + a10 + b0;
            out[r1 * N + c1] = resid[r1 * N + c1] + a11 + b1;
        }
    }
}

// ---------------- head-mean + bias + layernorm: 2 warps/row, 338 blocks -----
__global__ __launch_bounds__(64) void ln_kernel(const float* __restrict__ agg,
                                                const float* __restrict__ bias_l,
                                                const float* __restrict__ g,
                                                const float* __restrict__ bt,
                                                float* __restrict__ out)
{
    int lane = threadIdx.x & 31;
    int wrp = threadIdx.x >> 5;        // c-half
    int n = blockIdx.x;
    int b = (n >= N_) ? 1 : 0;
    int d = n - b * N_;
    int c = wrp * 128 + lane * 4;

    float4 v = make_float4(0.f, 0.f, 0.f, 0.f);
#pragma unroll
    for (int h = 0; h < H_; h++) {
        float4 t = *(const float4*)&agg[((size_t)(b * H_ + h) * N_ + d) * C_ + c];
        v.x += t.x; v.y += t.y; v.z += t.z; v.w += t.w;
    }
    float4 bb = *(const float4*)&bias_l[c];
    v.x = 0.25f * v.x + bb.x; v.y = 0.25f * v.y + bb.y;
    v.z = 0.25f * v.z + bb.z; v.w = 0.25f * v.w + bb.w;

    __shared__ float red[2][2];
    float s = v.x + v.y + v.z + v.w;
#pragma unroll
    for (int o = 16; o; o >>= 1) s += __shfl_xor_sync(0xffffffffu, s, o);
    if (lane == 0) red[0][wrp] = s;
    __syncthreads();
    float mu = (red[0][0] + red[0][1]) * (1.f / C_);

    float4 e = make_float4(v.x - mu, v.y - mu, v.z - mu, v.w - mu);
    float s2 = e.x * e.x + e.y * e.y + e.z * e.z + e.w * e.w;
#pragma unroll
    for (int o = 16; o; o >>= 1) s2 += __shfl_xor_sync(0xffffffffu, s2, o);
    if (lane == 0) red[1][wrp] = s2;
    __syncthreads();
    float rstd = rsqrtf((red[1][0] + red[1][1]) * (1.f / C_) + 1e-5f);

    float4 gg = *(const float4*)&g[c];
    float4 tb = *(const float4*)&bt[c];
    float4 o4;
    o4.x = e.x * rstd * gg.x + tb.x;
    o4.y = e.y * rstd * gg.y + tb.y;
    o4.z = e.z * rstd * gg.z + tb.z;
    o4.w = e.w * rstd * gg.w + tb.w;
    *(float4*)&out[(size_t)n * C_ + c] = o4;
}

// ---------------- final mean pool per graph ----------------------------------
__global__ void pool_kernel(const float* __restrict__ x, float* __restrict__ out)
{
    int b = blockIdx.x, t = threadIdx.x;
    float s = 0.f;
#pragma unroll 13
    for (int d = 0; d < N_; d++) s += x[(b * N_ + d) * C_ + t];
    out[b * C_ + t] = s * (1.f / N_);
}

// ---------------- host launcher -----------------------------------------------
extern "C" void kernel_launch(void* const* d_in, const int* in_sizes, int n_in,
                              void* d_out, int out_size)
{
    const float* x    = (const float*)d_in[0];
    const float* Wl   = (const float*)d_in[1];
    const float* bl   = (const float*)d_in[2];
    const float* Wr   = (const float*)d_in[3];
    const float* br   = (const float*)d_in[4];
    const float* att  = (const float*)d_in[5];
    const float* bias = (const float*)d_in[6];
    const float* lng  = (const float*)d_in[7];
    const float* lnb  = (const float*)d_in[8];
    const float* W1   = (const float*)d_in[9];
    const float* b1   = (const float*)d_in[10];
    const float* W2   = (const float*)d_in[11];
    const float* b2   = (const float*)d_in[12];

    float *bx, *bxl, *bxr, *bag, *bh, *bm, *bu, *bw;
    cudaGetSymbolAddress((void**)&bx,  g_x);
    cudaGetSymbolAddress((void**)&bxl, g_xl);
    cudaGetSymbolAddress((void**)&bxr, g_xr);
    cudaGetSymbolAddress((void**)&bag, g_agg);
    cudaGetSymbolAddress((void**)&bh,  g_h);
    cudaGetSymbolAddress((void**)&bm,  g_m);
    cudaGetSymbolAddress((void**)&bu,  g_u);
    cudaGetSymbolAddress((void**)&bw,  g_w);

    static int attr_done = 0;
    if (!attr_done) {
        cudaFuncSetAttribute(attn_agg_kernel,
                             cudaFuncAttributeMaxDynamicSharedMemorySize,
                             (int)ATTN_SMEM_BYTES);
        attr_done = 1;
    }

    for (int l = 0; l < L_; l++) {
        const float* xin = (l == 0) ? x : bx;
        gemm_dual<<<dim3(32, 6), 256>>>(xin,
                                        Wl + l * C_ * HC_, bl + l * HC_, bxl,
                                        Wr + l * C_ * HC_, br + l * HC_, bxr,
                                        NN_, C_);
        uw_kernel<<<NN_, 128>>>(bxl, bxr, att + l * H_ * C_, bu, bw);
        attn_agg_kernel<<<dim3(43, 8), 128, ATTN_SMEM_BYTES>>>(
            bxl, bxr, att + l * H_ * C_, bu, bw, bag);
        ln_kernel<<<NN_, 64>>>(bag, bias + l * C_, lng + l * C_, lnb + l * C_, bh);
        gemm_kernel<<<dim3(16, 11), 256>>>(bh, W1 + l * C_ * 2 * C_, b1 + l * 2 * C_,
                                           nullptr, bm, NN_, 2 * C_, C_, 1);
        gemm_kernel<<<dim3(8, 11), 256>>>(bm, W2 + l * 2 * C_ * C_, b2 + l * C_,
                                          xin, bx, NN_, C_, 2 * C_, 2);
    }

    pool_kernel<<<B_, 256>>>(bx, (float*)d_out);
}

// round 14
// speedup vs baseline: 1.1726x; 1.0027x over previous
#include <cuda_runtime.h>

#define B_   2
#define N_   169
#define NN_  338
#define C_   256
#define H_   4
#define HC_  1024
#define L_   3

typedef unsigned long long ull;

// ---------------- scratch (device globals) ---------------------------------
__device__ float g_x[NN_ * C_];               // running node features
__device__ float g_xl[NN_ * HC_];             // x @ Wl + bl
__device__ float g_xr[NN_ * HC_];             // x @ Wr + br
__device__ float g_agg[B_ * H_ * N_ * C_];    // per-head aggregation partials
__device__ float g_h[NN_ * C_];               // post layernorm
__device__ float g_m[NN_ * 2 * C_];           // mlp hidden
__device__ float g_u[H_ * NN_];               // <att, xl_n> per head
__device__ float g_w[H_ * NN_];               // <att, xr_n> per head

// ---------------- cp.async helpers ------------------------------------------
__device__ __forceinline__ unsigned s2u(const void* p)
{
    return (unsigned)__cvta_generic_to_shared(p);
}
__device__ __forceinline__ void cp16(unsigned dst, const void* src, bool ok)
{
    int sz = ok ? 16 : 0;
    asm volatile("cp.async.cg.shared.global [%0], [%1], 16, %2;"
                 :: "r"(dst), "l"(src), "r"(sz));
}
__device__ __forceinline__ void cp_commit()
{
    asm volatile("cp.async.commit_group;");
}
__device__ __forceinline__ void cp_wait0()
{
    asm volatile("cp.async.wait_group 0;" ::: "memory");
}

// ---------------- u/w rank-1 terms: u[h,n]=<att_h, xl[n,h,:]>, w likewise ---
__global__ __launch_bounds__(128) void uw_kernel(const float* __restrict__ xl,
                                                 const float* __restrict__ xr,
                                                 const float* __restrict__ att_l,
                                                 float* __restrict__ u,
                                                 float* __restrict__ w)
{
    int n = blockIdx.x;
    int h = threadIdx.x >> 5, lane = threadIdx.x & 31;
    const float4* xlp = (const float4*)&xl[(size_t)n * HC_ + h * C_];
    const float4* xrp = (const float4*)&xr[(size_t)n * HC_ + h * C_];
    const float4* ap  = (const float4*)&att_l[h * C_];
    float su = 0.f, sw = 0.f;
#pragma unroll
    for (int i = 0; i < 2; i++) {
        float4 a = ap[lane + 32 * i];
        float4 vl = xlp[lane + 32 * i];
        float4 vr = xrp[lane + 32 * i];
        su += a.x * vl.x + a.y * vl.y + a.z * vl.z + a.w * vl.w;
        sw += a.x * vr.x + a.y * vr.y + a.z * vr.z + a.w * vr.w;
    }
#pragma unroll
    for (int o = 16; o; o >>= 1) {
        su += __shfl_xor_sync(0xffffffffu, su, o);
        sw += __shfl_xor_sync(0xffffffffu, sw, o);
    }
    if (lane == 0) {
        u[h * NN_ + n] = su;
        w[h * NN_ + n] = sw;
    }
}

// ---------------- fused logits + softmax + aggregation ----------------------
// grid (43 d-tiles, 8 bh), block 128 = 4 warps. (R10 topology)
// Stride-36 XLs rows: 16B-aligned, perfect-permutation banks for LDS.128/STS.128.
// Staging via cp16 (12/thread/chunk), inner loop 4-channel (ulonglong2 reads).
struct AttnSmem {
    union {
        struct {
            float XLs[2][6][32][36];
            float XR[4][256];
            float A4[256];
        } pa;
        struct {
            float Xs[2][32][260];
        } pb;
    } u;
    float AL[4][193];
    float MX[4][2];
    float SS[4][2];
};
#define ATTN_SMEM_BYTES sizeof(AttnSmem)

__global__ __launch_bounds__(128) void attn_agg_kernel(const float* __restrict__ xl,
                                                       const float* __restrict__ xr,
                                                       const float* __restrict__ att_l,
                                                       const float* __restrict__ u,
                                                       const float* __restrict__ w,
                                                       float* __restrict__ agg)
{
    extern __shared__ __align__(16) char smem_raw[];
    AttnSmem* sm = (AttnSmem*)smem_raw;

    int tid = threadIdx.x;
    int lane = tid & 31;
    int wid = tid >> 5;
    int ty = wid >> 1;            // d-pair 0..1
    int hf = wid & 1;             // s-half: bands {0,1,2} or {3,4,5}
    int dt = blockIdx.x, bh = blockIdx.y;
    int b = bh >> 2, h = bh & 3;
    int d0 = dt * 4 + ty * 2;
    int d1 = d0 + 1;
    bool dok0 = d0 < N_, dok1 = d1 < N_;

    const float* xlh = xl + (size_t)b * N_ * HC_ + h * C_;

    // ---- stage chunk 0 of XLs (cp16: 1536 float4), then XR + A4 ----
#pragma unroll
    for (int i = 0; i < 12; i++) {
        int f = tid + 128 * i;          // 1536 float4 total
        int st = f >> 8;                // 256 float4 per band
        int rem = f & 255;
        int row = rem >> 3;
        int c4 = rem & 7;
        int s = st * 32 + row;
        bool ok = s < N_;
        cp16(s2u(&sm->u.pa.XLs[0][st][row][c4 * 4]),
             &xlh[(size_t)(ok ? s : 0) * HC_ + c4 * 4], ok);
    }
    cp_commit();
#pragma unroll
    for (int i = 0; i < 4; i++) {
        int f = tid + 128 * i;          // 512 float2 for XR[4][256]
        int row = f >> 7;
        int cc = (f & 127) * 2;
        int dr = dt * 4 + row;
        float2 v = make_float2(0.f, 0.f);
        if (dr < N_) v = *(const float2*)&xr[(size_t)(b * N_ + dr) * HC_ + h * C_ + cc];
        *(float2*)&sm->u.pa.XR[row][cc] = v;
    }
    {
        float2 a = *(const float2*)&att_l[h * C_ + tid * 2];
        sm->u.pa.A4[tid * 2]     = 0.4f * a.x;
        sm->u.pa.A4[tid * 2 + 1] = 0.4f * a.y;
    }

    ull acc0[3], acc1[3];
#pragma unroll
    for (int j = 0; j < 3; j++) { acc0[j] = 0ull; acc1[j] = 0ull; }
    const ull msk = 0x7FFFFFFF7FFFFFFFULL;

    // ---------------- Phase A: pipelined over 8 ck-chunks ----------------
#pragma unroll 1
    for (int ch = 0; ch < 8; ch++) {
        cp_wait0();
        __syncthreads();
        if (ch + 1 < 8) {
            int nb = (ch + 1) & 1;
            int ckn = (ch + 1) * 32;
#pragma unroll
            for (int i = 0; i < 12; i++) {
                int f = tid + 128 * i;
                int st = f >> 8;
                int rem = f & 255;
                int row = rem >> 3;
                int c4 = rem & 7;
                int s = st * 32 + row;
                bool ok = s < N_;
                cp16(s2u(&sm->u.pa.XLs[nb][st][row][c4 * 4]),
                     &xlh[(size_t)(ok ? s : 0) * HC_ + ckn + c4 * 4], ok);
            }
            cp_commit();
        }
        int bf = ch & 1;
        int ck = ch * 32;
#pragma unroll
        for (int c4 = 0; c4 < 8; c4++) {
            ulonglong2 r0 = *(const ulonglong2*)&sm->u.pa.XR[ty * 2][ck + c4 * 4];
            ulonglong2 r1 = *(const ulonglong2*)&sm->u.pa.XR[ty * 2 + 1][ck + c4 * 4];
            ulonglong2 a4 = *(const ulonglong2*)&sm->u.pa.A4[ck + c4 * 4];
#pragma unroll
            for (int j = 0; j < 3; j++) {
                ulonglong2 l = *(const ulonglong2*)&sm->u.pa.XLs[bf][hf * 3 + j][lane][c4 * 4];
                ull s, m;
                asm("add.rn.f32x2 %0, %1, %2;" : "=l"(s) : "l"(l.x), "l"(r0.x));
                asm("and.b64 %0, %1, %2;"      : "=l"(m) : "l"(s), "l"(msk));
                asm("fma.rn.f32x2 %0, %1, %2, %0;" : "+l"(acc0[j]) : "l"(m), "l"(a4.x));
                asm("add.rn.f32x2 %0, %1, %2;" : "=l"(s) : "l"(l.y), "l"(r0.y));
                asm("and.b64 %0, %1, %2;"      : "=l"(m) : "l"(s), "l"(msk));
                asm("fma.rn.f32x2 %0, %1, %2, %0;" : "+l"(acc0[j]) : "l"(m), "l"(a4.y));
                asm("add.rn.f32x2 %0, %1, %2;" : "=l"(s) : "l"(l.x), "l"(r1.x));
                asm("and.b64 %0, %1, %2;"      : "=l"(m) : "l"(s), "l"(msk));
                asm("fma.rn.f32x2 %0, %1, %2, %0;" : "+l"(acc1[j]) : "l"(m), "l"(a4.x));
                asm("add.rn.f32x2 %0, %1, %2;" : "=l"(s) : "l"(l.y), "l"(r1.y));
                asm("and.b64 %0, %1, %2;"      : "=l"(m) : "l"(s), "l"(msk));
                asm("fma.rn.f32x2 %0, %1, %2, %0;" : "+l"(acc1[j]) : "l"(m), "l"(a4.y));
            }
        }
        __syncthreads();
    }

    // ---- prefetch phase-B chunk 0 now; softmax hides its latency ----
#pragma unroll
    for (int i = 0; i < 16; i++) {
        int f = tid + 128 * i;          // 2048 float4
        int row = f >> 6, col4 = f & 63;
        int s = row;
        bool ok = s < N_;
        cp16(s2u(&sm->u.pb.Xs[0][row][col4 * 4]),
             &xlh[(size_t)(ok ? s : 0) * HC_ + col4 * 4], ok);
    }
    cp_commit();

    // ---------------- softmax (2 d-rows per warp, 2-warp combine) --------
    float w_d0 = dok0 ? w[h * NN_ + b * N_ + d0] : 0.f;
    float w_d1 = dok1 ? w[h * NN_ + b * N_ + d1] : 0.f;
    float lg0[3], lg1[3];
    float mx0 = -1e30f, mx1 = -1e30f;
#pragma unroll
    for (int j = 0; j < 3; j++) {
        int s = (hf * 3 + j) * 32 + lane;
        float uv = (s < N_) ? u[h * NN_ + b * N_ + s] : 0.f;
        {
            ull a = acc0[j];
            float lo = __uint_as_float((unsigned)(a & 0xffffffffu));
            float hi = __uint_as_float((unsigned)(a >> 32));
            float v = 0.6f * (uv + w_d0) + lo + hi;
            if (s >= N_ || s == d0) v = -1e30f;
            lg0[j] = v;
            mx0 = fmaxf(mx0, v);
        }
        {
            ull a = acc1[j];
            float lo = __uint_as_float((unsigned)(a & 0xffffffffu));
            float hi = __uint_as_float((unsigned)(a >> 32));
            float v = 0.6f * (uv + w_d1) + lo + hi;
            if (s >= N_ || s == d1) v = -1e30f;
            lg1[j] = v;
            mx1 = fmaxf(mx1, v);
        }
    }
#pragma unroll
    for (int o = 16; o; o >>= 1) {
        mx0 = fmaxf(mx0, __shfl_xor_sync(0xffffffffu, mx0, o));
        mx1 = fmaxf(mx1, __shfl_xor_sync(0xffffffffu, mx1, o));
    }
    if (lane == 0) {
        sm->MX[ty * 2][hf]     = mx0;
        sm->MX[ty * 2 + 1][hf] = mx1;
    }
    __syncthreads();
    float gmx0 = fmaxf(sm->MX[ty * 2][0],     sm->MX[ty * 2][1]);
    float gmx1 = fmaxf(sm->MX[ty * 2 + 1][0], sm->MX[ty * 2 + 1][1]);
    float sum0 = 0.f, sum1 = 0.f;
#pragma unroll
    for (int j = 0; j < 3; j++) {
        float e0 = __expf(lg0[j] - gmx0);
        float e1 = __expf(lg1[j] - gmx1);
        lg0[j] = e0; lg1[j] = e1;
        sum0 += e0; sum1 += e1;
    }
#pragma unroll
    for (int o = 16; o; o >>= 1) {
        sum0 += __shfl_xor_sync(0xffffffffu, sum0, o);
        sum1 += __shfl_xor_sync(0xffffffffu, sum1, o);
    }
    if (lane == 0) {
        sm->SS[ty * 2][hf]     = sum0;
        sm->SS[ty * 2 + 1][hf] = sum1;
    }
    __syncthreads();
    float inv0 = 1.f / (sm->SS[ty * 2][0]     + sm->SS[ty * 2][1]     + 1e-16f);
    float inv1 = 1.f / (sm->SS[ty * 2 + 1][0] + sm->SS[ty * 2 + 1][1] + 1e-16f);
#pragma unroll
    for (int j = 0; j < 3; j++) {
        sm->AL[ty * 2][(hf * 3 + j) * 32 + lane]     = lg0[j] * inv0;
        sm->AL[ty * 2 + 1][(hf * 3 + j) * 32 + lane] = lg1[j] * inv1;
    }
    // AL write -> read ordering provided by the __syncthreads at phase-B loop head

    // ---------------- Phase B: warp = (d-pair, c-half) -------------------
    float4 accA = make_float4(0.f, 0.f, 0.f, 0.f);   // d0
    float4 accB = make_float4(0.f, 0.f, 0.f, 0.f);   // d1
    int cb = hf * 128 + lane * 4;
#pragma unroll 1
    for (int ch = 0; ch < 6; ch++) {
        cp_wait0();
        __syncthreads();
        if (ch + 1 < 6) {
            int nb = (ch + 1) & 1;
            int skn = (ch + 1) * 32;
#pragma unroll
            for (int i = 0; i < 16; i++) {
                int f = tid + 128 * i;
                int row = f >> 6, col4 = f & 63;
                int s = skn + row;
                bool ok = s < N_;
                cp16(s2u(&sm->u.pb.Xs[nb][row][col4 * 4]),
                     &xlh[(size_t)(ok ? s : 0) * HC_ + col4 * 4], ok);
            }
            cp_commit();
        }
        int bf = ch & 1;
        int sk = ch * 32;
#pragma unroll
        for (int k = 0; k < 32; k++) {
            float av0 = sm->AL[ty * 2][sk + k];
            float av1 = sm->AL[ty * 2 + 1][sk + k];
            float4 x = *(const float4*)&sm->u.pb.Xs[bf][k][cb];
            accA.x = fmaf(av0, x.x, accA.x); accA.y = fmaf(av0, x.y, accA.y);
            accA.z = fmaf(av0, x.z, accA.z); accA.w = fmaf(av0, x.w, accA.w);
            accB.x = fmaf(av1, x.x, accB.x); accB.y = fmaf(av1, x.y, accB.y);
            accB.z = fmaf(av1, x.z, accB.z); accB.w = fmaf(av1, x.w, accB.w);
        }
        __syncthreads();
    }

    if (dok0)
        *(float4*)&agg[((size_t)bh * N_ + d0) * C_ + cb] = accA;
    if (dok1)
        *(float4*)&agg[((size_t)bh * N_ + d1) * C_ + cb] = accB;
}

// ---------------- fused xl/xr GEMM: 64x64 tile, 4x4/thread, cp.async --------
__global__ __launch_bounds__(256) void gemm_dual(const float* __restrict__ A,
                                                 const float* __restrict__ B1,
                                                 const float* __restrict__ c1,
                                                 float* __restrict__ o1,
                                                 const float* __restrict__ B2,
                                                 const float* __restrict__ c2p,
                                                 float* __restrict__ o2,
                                                 int M, int K)
{
    __shared__ __align__(16) float As[2][64][36];
    __shared__ __align__(16) float Bs[2][32][68];

    const float* Bm;
    const float* bias;
    float* out;
    int n0;
    if (blockIdx.x < 16) { Bm = B1; bias = c1;  out = o1; n0 = blockIdx.x * 64; }
    else                 { Bm = B2; bias = c2p; out = o2; n0 = (blockIdx.x - 16) * 64; }

    int tid = threadIdx.x;
    int tx = tid & 15, ty = tid >> 4;
    int m0 = blockIdx.y * 64;

    int a_row = tid >> 2, a_c4a = (tid & 3) * 2;
    int b_row0 = tid >> 4, b_c4 = tid & 15;

    {
        bool okA = (m0 + a_row) < M;
        const float* srcA = &A[(size_t)(m0 + (okA ? a_row : 0)) * K + a_c4a * 4];
        cp16(s2u(&As[0][a_row][a_c4a * 4]), srcA, okA);
        cp16(s2u(&As[0][a_row][(a_c4a + 1) * 4]), srcA + 4, okA);
        cp16(s2u(&Bs[0][b_row0][b_c4 * 4]),
             &Bm[(size_t)b_row0 * HC_ + n0 + b_c4 * 4], true);
        cp16(s2u(&Bs[0][b_row0 + 16][b_c4 * 4]),
             &Bm[(size_t)(b_row0 + 16) * HC_ + n0 + b_c4 * 4], true);
    }
    cp_commit();

    float acc[4][4];
#pragma unroll
    for (int i = 0; i < 4; i++)
#pragma unroll
        for (int j = 0; j < 4; j++) acc[i][j] = 0.f;

    int nch = K / 32;
#pragma unroll 1
    for (int ch = 0; ch < nch; ch++) {
        cp_wait0();
        __syncthreads();
        if (ch + 1 < nch) {
            int nb = (ch + 1) & 1;
            int kkn = (ch + 1) * 32;
            bool okA = (m0 + a_row) < M;
            const float* srcA = &A[(size_t)(m0 + (okA ? a_row : 0)) * K + kkn + a_c4a * 4];
            cp16(s2u(&As[nb][a_row][a_c4a * 4]), srcA, okA);
            cp16(s2u(&As[nb][a_row][(a_c4a + 1) * 4]), srcA + 4, okA);
            cp16(s2u(&Bs[nb][b_row0][b_c4 * 4]),
                 &Bm[(size_t)(kkn + b_row0) * HC_ + n0 + b_c4 * 4], true);
            cp16(s2u(&Bs[nb][b_row0 + 16][b_c4 * 4]),
                 &Bm[(size_t)(kkn + b_row0 + 16) * HC_ + n0 + b_c4 * 4], true);
            cp_commit();
        }
        int bf = ch & 1;
#pragma unroll
        for (int k = 0; k < 32; k++) {
            float a0 = As[bf][ty * 4 + 0][k];
            float a1 = As[bf][ty * 4 + 1][k];
            float a2 = As[bf][ty * 4 + 2][k];
            float a3 = As[bf][ty * 4 + 3][k];
            float4 bv = *(const float4*)&Bs[bf][k][tx * 4];
            acc[0][0] = fmaf(a0, bv.x, acc[0][0]); acc[0][1] = fmaf(a0, bv.y, acc[0][1]);
            acc[0][2] = fmaf(a0, bv.z, acc[0][2]); acc[0][3] = fmaf(a0, bv.w, acc[0][3]);
            acc[1][0] = fmaf(a1, bv.x, acc[1][0]); acc[1][1] = fmaf(a1, bv.y, acc[1][1]);
            acc[1][2] = fmaf(a1, bv.z, acc[1][2]); acc[1][3] = fmaf(a1, bv.w, acc[1][3]);
            acc[2][0] = fmaf(a2, bv.x, acc[2][0]); acc[2][1] = fmaf(a2, bv.y, acc[2][1]);
            acc[2][2] = fmaf(a2, bv.z, acc[2][2]); acc[2][3] = fmaf(a2, bv.w, acc[2][3]);
            acc[3][0] = fmaf(a3, bv.x, acc[3][0]); acc[3][1] = fmaf(a3, bv.y, acc[3][1]);
            acc[3][2] = fmaf(a3, bv.z, acc[3][2]); acc[3][3] = fmaf(a3, bv.w, acc[3][3]);
        }
        __syncthreads();
    }

    float4 bb = *(const float4*)&bias[n0 + tx * 4];
#pragma unroll
    for (int i = 0; i < 4; i++) {
        int r = m0 + ty * 4 + i;
        if (r < M) {
            float4 o4;
            o4.x = acc[i][0] + bb.x;
            o4.y = acc[i][1] + bb.y;
            o4.z = acc[i][2] + bb.z;
            o4.w = acc[i][3] + bb.w;
            *(float4*)&out[(size_t)r * HC_ + n0 + tx * 4] = o4;
        }
    }
}

// ---------------- generic 32x32 GEMM, cp.async double-buffered --------------
// mode: 1 relu, 2 residual: out = resid + acc + bias
__global__ void gemm_kernel(const float* __restrict__ A,
                            const float* __restrict__ Bm,
                            const float* __restrict__ bias,
                            const float* __restrict__ resid,
                            float* __restrict__ out,
                            int M, int N, int K, int mode)
{
    __shared__ __align__(16) float As[2][32][36];
    __shared__ __align__(16) float Bs[2][32][36];
    int tid = threadIdx.x;
    int tx = tid & 15, ty = tid >> 4;
    int m0 = blockIdx.y * 32;
    int n0 = blockIdx.x * 32;
    int lr = tid >> 3, lc4 = tid & 7;
    float a00 = 0.f, a01 = 0.f, a10 = 0.f, a11 = 0.f;

    {
        bool okA = (m0 + lr) < M;
        cp16(s2u(&As[0][lr][lc4 * 4]),
             &A[(size_t)(m0 + (okA ? lr : 0)) * K + lc4 * 4], okA);
        cp16(s2u(&Bs[0][lr][lc4 * 4]),
             &Bm[(size_t)lr * N + n0 + lc4 * 4], true);
    }
    cp_commit();

    int nch = K / 32;
#pragma unroll 1
    for (int ch = 0; ch < nch; ch++) {
        cp_wait0();
        __syncthreads();
        if (ch + 1 < nch) {
            int nb = (ch + 1) & 1;
            int kkn = (ch + 1) * 32;
            bool okA = (m0 + lr) < M;
            cp16(s2u(&As[nb][lr][lc4 * 4]),
                 &A[(size_t)(m0 + (okA ? lr : 0)) * K + kkn + lc4 * 4], okA);
            cp16(s2u(&Bs[nb][lr][lc4 * 4]),
                 &Bm[(size_t)(kkn + lr) * N + n0 + lc4 * 4], true);
            cp_commit();
        }
        int bf = ch & 1;
#pragma unroll
        for (int k = 0; k < 32; k++) {
            float av0 = As[bf][ty][k],      av1 = As[bf][ty + 16][k];
            float bv0 = Bs[bf][k][tx],      bv1 = Bs[bf][k][tx + 16];
            a00 = fmaf(av0, bv0, a00);  a01 = fmaf(av0, bv1, a01);
            a10 = fmaf(av1, bv0, a10);  a11 = fmaf(av1, bv1, a11);
        }
        __syncthreads();
    }

    int r0 = m0 + ty, r1 = m0 + ty + 16;
    int c0 = n0 + tx, c1 = n0 + tx + 16;
    float b0 = bias[c0], b1 = bias[c1];
    if (mode == 1) {
        if (r0 < M) { out[r0 * N + c0] = fmaxf(a00 + b0, 0.f); out[r0 * N + c1] = fmaxf(a01 + b1, 0.f); }
        if (r1 < M) { out[r1 * N + c0] = fmaxf(a10 + b0, 0.f); out[r1 * N + c1] = fmaxf(a11 + b1, 0.f); }
    } else {
        if (r0 < M) {
            out[r0 * N + c0] = resid[r0 * N + c0] + a00 + b0;
            out[r0 * N + c1] = resid[r0 * N + c1] + a01 + b1;
        }
        if (r1 < M) {
            out[r1 * N + c0] = resid[r1 * N + c0] + a10 + b0;
            out[r1 * N + c1] = resid[r1 * N + c1] + a11 + b1;
        }
    }
}

// ---------------- head-mean + bias + layernorm: 2 warps/row, 338 blocks -----
__global__ __launch_bounds__(64) void ln_kernel(const float* __restrict__ agg,
                                                const float* __restrict__ bias_l,
                                                const float* __restrict__ g,
                                                const float* __restrict__ bt,
                                                float* __restrict__ out)
{
    int lane = threadIdx.x & 31;
    int wrp = threadIdx.x >> 5;
    int n = blockIdx.x;
    int b = (n >= N_) ? 1 : 0;
    int d = n - b * N_;
    int c = wrp * 128 + lane * 4;

    float4 v = make_float4(0.f, 0.f, 0.f, 0.f);
#pragma unroll
    for (int h = 0; h < H_; h++) {
        float4 t = *(const float4*)&agg[((size_t)(b * H_ + h) * N_ + d) * C_ + c];
        v.x += t.x; v.y += t.y; v.z += t.z; v.w += t.w;
    }
    float4 bb = *(const float4*)&bias_l[c];
    v.x = 0.25f * v.x + bb.x; v.y = 0.25f * v.y + bb.y;
    v.z = 0.25f * v.z + bb.z; v.w = 0.25f * v.w + bb.w;

    __shared__ float red[2][2];
    float s = v.x + v.y + v.z + v.w;
#pragma unroll
    for (int o = 16; o; o >>= 1) s += __shfl_xor_sync(0xffffffffu, s, o);
    if (lane == 0) red[0][wrp] = s;
    __syncthreads();
    float mu = (red[0][0] + red[0][1]) * (1.f / C_);

    float4 e = make_float4(v.x - mu, v.y - mu, v.z - mu, v.w - mu);
    float s2 = e.x * e.x + e.y * e.y + e.z * e.z + e.w * e.w;
#pragma unroll
    for (int o = 16; o; o >>= 1) s2 += __shfl_xor_sync(0xffffffffu, s2, o);
    if (lane == 0) red[1][wrp] = s2;
    __syncthreads();
    float rstd = rsqrtf((red[1][0] + red[1][1]) * (1.f / C_) + 1e-5f);

    float4 gg = *(const float4*)&g[c];
    float4 tb = *(const float4*)&bt[c];
    float4 o4;
    o4.x = e.x * rstd * gg.x + tb.x;
    o4.y = e.y * rstd * gg.y + tb.y;
    o4.z = e.z * rstd * gg.z + tb.z;
    o4.w = e.w * rstd * gg.w + tb.w;
    *(float4*)&out[(size_t)n * C_ + c] = o4;
}

// ---------------- final mean pool per graph ----------------------------------
__global__ void pool_kernel(const float* __restrict__ x, float* __restrict__ out)
{
    int b = blockIdx.x, t = threadIdx.x;
    float s = 0.f;
#pragma unroll 13
    for (int d = 0; d < N_; d++) s += x[(b * N_ + d) * C_ + t];
    out[b * C_ + t] = s * (1.f / N_);
}

// ---------------- host launcher -----------------------------------------------
extern "C" void kernel_launch(void* const* d_in, const int* in_sizes, int n_in,
                              void* d_out, int out_size)
{
    const float* x    = (const float*)d_in[0];
    const float* Wl   = (const float*)d_in[1];
    const float* bl   = (const float*)d_in[2];
    const float* Wr   = (const float*)d_in[3];
    const float* br   = (const float*)d_in[4];
    const float* att  = (const float*)d_in[5];
    const float* bias = (const float*)d_in[6];
    const float* lng  = (const float*)d_in[7];
    const float* lnb  = (const float*)d_in[8];
    const float* W1   = (const float*)d_in[9];
    const float* b1   = (const float*)d_in[10];
    const float* W2   = (const float*)d_in[11];
    const float* b2   = (const float*)d_in[12];

    float *bx, *bxl, *bxr, *bag, *bh, *bm, *bu, *bw;
    cudaGetSymbolAddress((void**)&bx,  g_x);
    cudaGetSymbolAddress((void**)&bxl, g_xl);
    cudaGetSymbolAddress((void**)&bxr, g_xr);
    cudaGetSymbolAddress((void**)&bag, g_agg);
    cudaGetSymbolAddress((void**)&bh,  g_h);
    cudaGetSymbolAddress((void**)&bm,  g_m);
    cudaGetSymbolAddress((void**)&bu,  g_u);
    cudaGetSymbolAddress((void**)&bw,  g_w);

    static int attr_done = 0;
    if (!attr_done) {
        cudaFuncSetAttribute(attn_agg_kernel,
                             cudaFuncAttributeMaxDynamicSharedMemorySize,
                             (int)ATTN_SMEM_BYTES);
        attr_done = 1;
    }

    for (int l = 0; l < L_; l++) {
        const float* xin = (l == 0) ? x : bx;
        gemm_dual<<<dim3(32, 6), 256>>>(xin,
                                        Wl + l * C_ * HC_, bl + l * HC_, bxl,
                                        Wr + l * C_ * HC_, br + l * HC_, bxr,
                                        NN_, C_);
        uw_kernel<<<NN_, 128>>>(bxl, bxr, att + l * H_ * C_, bu, bw);
        attn_agg_kernel<<<dim3(43, 8), 128, ATTN_SMEM_BYTES>>>(
            bxl, bxr, att + l * H_ * C_, bu, bw, bag);
        ln_kernel<<<NN_, 64>>>(bag, bias + l * C_, lng + l * C_, lnb + l * C_, bh);
        gemm_kernel<<<dim3(16, 11), 256>>>(bh, W1 + l * C_ * 2 * C_, b1 + l * 2 * C_,
                                           nullptr, bm, NN_, 2 * C_, C_, 1);
        gemm_kernel<<<dim3(8, 11), 256>>>(bm, W2 + l * 2 * C_ * C_, b2 + l * C_,
                                          xin, bx, NN_, C_, 2 * C_, 2);
    }

    pool_kernel<<<B_, 256>>>(bx, (float*)d_out);
}